// round 1
// baseline (speedup 1.0000x reference)
#include <cuda_runtime.h>

#define KPS   39
#define DIN   78
#define DHID  195
#define TB    64       // tokens per block
#define NT    256      // threads per block

// shared layout strides (floats)
#define W1T_STRIDE 196   // [DIN][196]  w1t[d][h]
#define W2T_STRIDE 80    // [DHID][80]  w2t[h][d]
#define J_STRIDE   68    // [DIN][68]   js[d][t]
#define H1_STRIDE  68    // [DHID][68]  h1[h][t]
#define H2_STRIDE  80    // [TB][80]    h2[t][d]

// float offsets into dynamic smem
#define OFS_W1T 0
#define OFS_W2T (OFS_W1T + DIN*W1T_STRIDE + 32)          // 15320
#define OFS_J   (OFS_W2T + DHID*W2T_STRIDE)              // 30920
#define OFS_H1  (OFS_J   + DIN*J_STRIDE)                 // 36224
#define OFS_H2  (OFS_H1  + DHID*H1_STRIDE)               // 49484
#define OFS_B1  (OFS_H2  + TB*H2_STRIDE)                 // 54604
#define OFS_AL1 (OFS_B1  + DHID)
#define OFS_BE1 (OFS_AL1 + DHID)
#define OFS_B2  (OFS_BE1 + DHID)
#define OFS_AL2 (OFS_B2  + DIN)
#define OFS_BE2 (OFS_AL2 + DIN)
#define SMEM_FLOATS (OFS_BE2 + DIN)                      // 55423

__global__ __launch_bounds__(NT)
void spatialctx_fused_kernel(
    const float* __restrict__ x, const float* __restrict__ y,
    const float* __restrict__ W1, const float* __restrict__ b1,
    const float* __restrict__ W2, const float* __restrict__ b2,
    const float* __restrict__ a1, const float* __restrict__ a2,
    const float* __restrict__ alpha1, const float* __restrict__ beta1,
    const float* __restrict__ alpha2, const float* __restrict__ beta2,
    float* __restrict__ out, int ntok)
{
    extern __shared__ float sm[];
    float* w1t  = sm + OFS_W1T;
    float* w2t  = sm + OFS_W2T;
    float* js   = sm + OFS_J;
    float* h1   = sm + OFS_H1;
    float* h2   = sm + OFS_H2;
    float* sb1  = sm + OFS_B1;
    float* sal1 = sm + OFS_AL1;
    float* sbe1 = sm + OFS_BE1;
    float* sb2  = sm + OFS_B2;
    float* sal2 = sm + OFS_AL2;
    float* sbe2 = sm + OFS_BE2;

    const int tid  = threadIdx.x;
    const int base = blockIdx.x * TB;

    // ---- stage weights (transposed) + params into shared ----
    for (int i = tid; i < DHID * DIN; i += NT) {
        int h = i / DIN, d = i - h * DIN;       // W1 is [DHID, DIN] row-major
        w1t[d * W1T_STRIDE + h] = W1[i];
    }
    for (int i = tid; i < DIN * DHID; i += NT) {
        int d = i / DHID, h = i - d * DHID;     // W2 is [DIN, DHID] row-major
        w2t[h * W2T_STRIDE + d] = W2[i];
    }
    for (int i = tid; i < DHID; i += NT) {
        sb1[i] = b1[i]; sal1[i] = alpha1[i]; sbe1[i] = beta1[i];
    }
    for (int i = tid; i < DIN; i += NT) {
        sb2[i] = b2[i]; sal2[i] = alpha2[i]; sbe2[i] = beta2[i];
    }
    // ---- joined tile: js[d][t] ----
    for (int i = tid; i < TB * DIN; i += NT) {
        int t = i / DIN, d = i - t * DIN;
        int gt = base + t;
        float v = 0.f;
        if (gt < ntok)
            v = (d < KPS) ? x[(size_t)gt * KPS + d] : y[(size_t)gt * KPS + d - KPS];
        js[d * J_STRIDE + t] = v;
    }
    const float a1v = a1[0];
    const float a2v = a2[0];
    __syncthreads();

    const int tx = tid & 15;   // token group: tokens tx*4 .. tx*4+3
    const int ty = tid >> 4;   // feature group: features ty + 16*j

    // ================= GEMM1: h1[h][t] = joined @ W1^T =================
    float acc[13][4];
    #pragma unroll
    for (int j = 0; j < 13; j++)
        #pragma unroll
        for (int i = 0; i < 4; i++) acc[j][i] = 0.f;

    #pragma unroll 2
    for (int d = 0; d < DIN; d++) {
        float4 jv = *(const float4*)&js[d * J_STRIDE + tx * 4];
        const float* wrow = &w1t[d * W1T_STRIDE + ty];
        #pragma unroll
        for (int j = 0; j < 13; j++) {
            float w = wrow[16 * j];
            acc[j][0] += jv.x * w;
            acc[j][1] += jv.y * w;
            acc[j][2] += jv.z * w;
            acc[j][3] += jv.w * w;
        }
    }
    // bias + PReLU, store to h1 (only valid hidden rows)
    #pragma unroll
    for (int j = 0; j < 13; j++) {
        int hh = ty + 16 * j;
        if (hh < DHID) {
            float bb = sb1[hh];
            #pragma unroll
            for (int i = 0; i < 4; i++) {
                float v = acc[j][i] + bb;
                v = (v >= 0.f) ? v : a1v * v;
                h1[hh * H1_STRIDE + tx * 4 + i] = v;
            }
        }
    }
    __syncthreads();

    // ================= LayerNorm over DHID (4 threads / token) =========
    const int lt   = tid >> 2;  // token 0..63
    const int part = tid & 3;
    {
        float s = 0.f, ss = 0.f;
        for (int h = part; h < DHID; h += 4) {
            float v = h1[h * H1_STRIDE + lt];
            s += v; ss += v * v;
        }
        s  += __shfl_xor_sync(0xffffffffu, s, 1);
        ss += __shfl_xor_sync(0xffffffffu, ss, 1);
        s  += __shfl_xor_sync(0xffffffffu, s, 2);
        ss += __shfl_xor_sync(0xffffffffu, ss, 2);
        float mean = s * (1.f / DHID);
        float var  = ss * (1.f / DHID) - mean * mean;
        float rstd = rsqrtf(var + 1e-5f);
        for (int h = part; h < DHID; h += 4) {
            float v = h1[h * H1_STRIDE + lt];
            h1[h * H1_STRIDE + lt] = (v - mean) * rstd * sal1[h] + sbe1[h];
        }
    }
    __syncthreads();

    // ================= GEMM2: h2[t][d] = h1n @ W2^T ====================
    float acc2[5][4];
    #pragma unroll
    for (int j = 0; j < 5; j++)
        #pragma unroll
        for (int i = 0; i < 4; i++) acc2[j][i] = 0.f;

    #pragma unroll 3
    for (int h = 0; h < DHID; h++) {
        float4 hv = *(const float4*)&h1[h * H1_STRIDE + tx * 4];
        const float* wrow = &w2t[h * W2T_STRIDE + ty];
        #pragma unroll
        for (int j = 0; j < 5; j++) {
            float w = wrow[16 * j];   // ty+64 <= 79 < 80: stays in padded row
            acc2[j][0] += hv.x * w;
            acc2[j][1] += hv.y * w;
            acc2[j][2] += hv.z * w;
            acc2[j][3] += hv.w * w;
        }
    }
    #pragma unroll
    for (int j = 0; j < 5; j++) {
        int dd = ty + 16 * j;
        if (dd < DIN) {
            float bb = sb2[dd];
            #pragma unroll
            for (int i = 0; i < 4; i++) {
                float v = acc2[j][i] + bb;
                v = (v >= 0.f) ? v : a2v * v;
                h2[(tx * 4 + i) * H2_STRIDE + dd] = v;
            }
        }
    }
    __syncthreads();

    // ======= LayerNorm over DIN + residual + split-store ===============
    {
        float s = 0.f, ss = 0.f;
        for (int d = part; d < DIN; d += 4) {
            float v = h2[lt * H2_STRIDE + d];
            s += v; ss += v * v;
        }
        s  += __shfl_xor_sync(0xffffffffu, s, 1);
        ss += __shfl_xor_sync(0xffffffffu, ss, 1);
        s  += __shfl_xor_sync(0xffffffffu, s, 2);
        ss += __shfl_xor_sync(0xffffffffu, ss, 2);
        float mean = s * (1.f / DIN);
        float var  = ss * (1.f / DIN) - mean * mean;
        float rstd = rsqrtf(var + 1e-5f);

        int gt = base + lt;
        if (gt < ntok) {
            size_t half = (size_t)ntok * KPS;
            for (int d = part; d < DIN; d += 4) {
                float v = h2[lt * H2_STRIDE + d];
                float r = (v - mean) * rstd * sal2[d] + sbe2[d] + js[d * J_STRIDE + lt];
                size_t o = (d < KPS) ? ((size_t)gt * KPS + d)
                                     : (half + (size_t)gt * KPS + (d - KPS));
                out[o] = r;
            }
        }
    }
}

extern "C" void kernel_launch(void* const* d_in, const int* in_sizes, int n_in,
                              void* d_out, int out_size) {
    const float* x      = (const float*)d_in[0];
    const float* y      = (const float*)d_in[1];
    const float* W1     = (const float*)d_in[2];
    const float* b1     = (const float*)d_in[3];
    const float* W2     = (const float*)d_in[4];
    const float* b2     = (const float*)d_in[5];
    const float* a1     = (const float*)d_in[6];
    const float* a2     = (const float*)d_in[7];
    const float* alpha1 = (const float*)d_in[8];
    const float* beta1  = (const float*)d_in[9];
    const float* alpha2 = (const float*)d_in[10];
    const float* beta2  = (const float*)d_in[11];
    float* out = (float*)d_out;

    int ntok = in_sizes[0] / KPS;
    int grid = (ntok + TB - 1) / TB;
    size_t smem = SMEM_FLOATS * sizeof(float);

    cudaFuncSetAttribute(spatialctx_fused_kernel,
                         cudaFuncAttributeMaxDynamicSharedMemorySize, (int)smem);
    spatialctx_fused_kernel<<<grid, NT, smem>>>(
        x, y, W1, b1, W2, b2, a1, a2, alpha1, beta1, alpha2, beta2, out, ntok);
}

// round 2
// speedup vs baseline: 1.7373x; 1.7373x over previous
#include <cuda_runtime.h>

#define KPS   39
#define DIN   78
#define DHID  195
#define TB    128      // tokens per block
#define NT    256      // threads per block (8 warps, 16 tokens each)

// padded dims
#define DIN_P   80     // K of GEMM1 / N of GEMM2, 10 k-tiles / 10 n-tiles
#define DHID_P  200    // N of GEMM1 / K of GEMM2, 25 n-tiles / 25 k-tiles

// smem strides (floats) — chosen so all mma fragment loads are bank-conflict-free
#define W1_STRIDE 84    // w1s[n][k]  n<200, k<80   bank=(20n+k)%32 distinct
#define W2_STRIDE 204   // w2s[n][k]  n<80,  k<200  bank=(12n+k)%32 distinct
#define J_STRIDE  84    // js[t][d]   t<128, d<80
#define H1_STRIDE 204   // h1[t][h]   t<128, h<200

// float offsets into dynamic smem
#define OFS_W   0                              // 16800 floats (w1s 200x84; w2s 80x204=16320 overlays)
#define OFS_J   16800                          // 128*84 = 10752
#define OFS_H1  27552                          // 128*204 = 26112
#define OFS_B1  53664                          // 200
#define OFS_AL1 53864
#define OFS_BE1 54064
#define OFS_B2  54264                          // 80
#define OFS_AL2 54344
#define OFS_BE2 54424
#define SMEM_FLOATS 54504                      // 218016 bytes

__device__ __forceinline__ float tf32r(float f) {
    unsigned u;
    asm("cvt.rna.tf32.f32 %0, %1;" : "=r"(u) : "f"(f));
    return __uint_as_float(u);
}

__device__ __forceinline__ void mma_tf32(float c[4],
                                         unsigned a0, unsigned a1, unsigned a2, unsigned a3,
                                         unsigned b0, unsigned b1) {
    asm volatile(
        "mma.sync.aligned.m16n8k8.row.col.f32.tf32.tf32.f32 "
        "{%0,%1,%2,%3}, {%4,%5,%6,%7}, {%8,%9}, {%0,%1,%2,%3};"
        : "+f"(c[0]), "+f"(c[1]), "+f"(c[2]), "+f"(c[3])
        : "r"(a0), "r"(a1), "r"(a2), "r"(a3), "r"(b0), "r"(b1));
}

__global__ __launch_bounds__(NT)
void spatialctx_tc_kernel(
    const float* __restrict__ x, const float* __restrict__ y,
    const float* __restrict__ W1, const float* __restrict__ b1,
    const float* __restrict__ W2, const float* __restrict__ b2,
    const float* __restrict__ a1, const float* __restrict__ a2,
    const float* __restrict__ alpha1, const float* __restrict__ beta1,
    const float* __restrict__ alpha2, const float* __restrict__ beta2,
    float* __restrict__ out, int ntok)
{
    extern __shared__ float sm[];
    float* ws   = sm + OFS_W;     // w1s then (after sync) w2s
    float* js   = sm + OFS_J;
    float* h1   = sm + OFS_H1;
    float* b1s  = sm + OFS_B1;
    float* al1s = sm + OFS_AL1;
    float* be1s = sm + OFS_BE1;
    float* b2s  = sm + OFS_B2;
    float* al2s = sm + OFS_AL2;
    float* be2s = sm + OFS_BE2;

    const int tid  = threadIdx.x;
    const int base = blockIdx.x * TB;

    // ---- stage W1 (tf32-rounded, zero-padded) ----
    for (int i = tid; i < DHID_P * DIN_P; i += NT) {
        int n = i / DIN_P, k = i - n * DIN_P;
        float v = (n < DHID && k < DIN) ? W1[n * DIN + k] : 0.f;
        ws[n * W1_STRIDE + k] = tf32r(v);
    }
    // ---- stage joined (exact fp32: residual needs it unrounded) ----
    for (int i = tid; i < TB * DIN_P; i += NT) {
        int t = i / DIN_P, d = i - t * DIN_P;
        int gt = base + t;
        float v = 0.f;
        if (gt < ntok && d < DIN)
            v = (d < KPS) ? x[(size_t)gt * KPS + d] : y[(size_t)gt * KPS + d - KPS];
        js[t * J_STRIDE + d] = v;
    }
    // ---- params (zero-padded) ----
    for (int i = tid; i < DHID_P; i += NT) {
        b1s[i]  = (i < DHID) ? b1[i]     : 0.f;
        al1s[i] = (i < DHID) ? alpha1[i] : 0.f;
        be1s[i] = (i < DHID) ? beta1[i]  : 0.f;
    }
    for (int i = tid; i < DIN_P; i += NT) {
        b2s[i]  = (i < DIN) ? b2[i]     : 0.f;
        al2s[i] = (i < DIN) ? alpha2[i] : 0.f;
        be2s[i] = (i < DIN) ? beta2[i]  : 0.f;
    }
    const float a1v = a1[0];
    const float a2v = a2[0];
    __syncthreads();

    const int warp   = tid >> 5;
    const int lane   = tid & 31;
    const int r      = lane >> 2;     // group id: rows r, r+8
    const int tig    = lane & 3;      // thread-in-group
    const int tokrow = warp * 16;

    // ================= GEMM1 (tensor): C[16tok x 200hid] per warp =======
    float acc[25][4];
    #pragma unroll
    for (int nt = 0; nt < 25; nt++)
        #pragma unroll
        for (int i = 0; i < 4; i++) acc[nt][i] = 0.f;

    {
        const float* aptr = js + (tokrow + r) * J_STRIDE + tig;
        const float* bptr = ws + r * W1_STRIDE + tig;
        #pragma unroll 1
        for (int kt = 0; kt < 10; kt++) {
            unsigned a0 = __float_as_uint(tf32r(aptr[kt * 8 + 0]));
            unsigned a2 = __float_as_uint(tf32r(aptr[kt * 8 + 4]));
            unsigned a1f = __float_as_uint(tf32r(aptr[kt * 8 + 8 * J_STRIDE + 0]));
            unsigned a3 = __float_as_uint(tf32r(aptr[kt * 8 + 8 * J_STRIDE + 4]));
            #pragma unroll
            for (int nt = 0; nt < 25; nt++) {
                const float* bp = bptr + nt * 8 * W1_STRIDE + kt * 8;
                unsigned b0 = __float_as_uint(bp[0]);
                unsigned b1f = __float_as_uint(bp[4]);
                mma_tf32(acc[nt], a0, a1f, a2, a3, b0, b1f);
            }
        }
    }

    // ======== bias + PReLU + LayerNorm(195) in-register ================
    {
        float s0 = 0.f, q0 = 0.f, s1 = 0.f, q1 = 0.f;
        #pragma unroll
        for (int nt = 0; nt < 25; nt++) {
            int f0 = nt * 8 + 2 * tig;
            float2 bb = *(const float2*)&b1s[f0];
            float v;
            v = acc[nt][0] + bb.x; v = (v >= 0.f) ? v : a1v * v; if (f0     >= DHID) v = 0.f;
            acc[nt][0] = v; s0 += v; q0 += v * v;
            v = acc[nt][1] + bb.y; v = (v >= 0.f) ? v : a1v * v; if (f0 + 1 >= DHID) v = 0.f;
            acc[nt][1] = v; s0 += v; q0 += v * v;
            v = acc[nt][2] + bb.x; v = (v >= 0.f) ? v : a1v * v; if (f0     >= DHID) v = 0.f;
            acc[nt][2] = v; s1 += v; q1 += v * v;
            v = acc[nt][3] + bb.y; v = (v >= 0.f) ? v : a1v * v; if (f0 + 1 >= DHID) v = 0.f;
            acc[nt][3] = v; s1 += v; q1 += v * v;
        }
        s0 += __shfl_xor_sync(0xffffffffu, s0, 1); q0 += __shfl_xor_sync(0xffffffffu, q0, 1);
        s1 += __shfl_xor_sync(0xffffffffu, s1, 1); q1 += __shfl_xor_sync(0xffffffffu, q1, 1);
        s0 += __shfl_xor_sync(0xffffffffu, s0, 2); q0 += __shfl_xor_sync(0xffffffffu, q0, 2);
        s1 += __shfl_xor_sync(0xffffffffu, s1, 2); q1 += __shfl_xor_sync(0xffffffffu, q1, 2);
        float m0 = s0 * (1.f / DHID), m1 = s1 * (1.f / DHID);
        float r0 = rsqrtf(q0 * (1.f / DHID) - m0 * m0 + 1e-5f);
        float r1 = rsqrtf(q1 * (1.f / DHID) - m1 * m1 + 1e-5f);

        float* h1w0 = h1 + (tokrow + r) * H1_STRIDE;
        float* h1w1 = h1 + (tokrow + r + 8) * H1_STRIDE;
        #pragma unroll
        for (int nt = 0; nt < 25; nt++) {
            int f0 = nt * 8 + 2 * tig;
            float2 aa = *(const float2*)&al1s[f0];
            float2 be = *(const float2*)&be1s[f0];
            float2 o0, o1;
            o0.x = tf32r((acc[nt][0] - m0) * r0 * aa.x + be.x);
            o0.y = tf32r((acc[nt][1] - m0) * r0 * aa.y + be.y);
            o1.x = tf32r((acc[nt][2] - m1) * r1 * aa.x + be.x);
            o1.y = tf32r((acc[nt][3] - m1) * r1 * aa.y + be.y);
            *(float2*)&h1w0[f0] = o0;
            *(float2*)&h1w1[f0] = o1;
        }
    }
    __syncthreads();

    // ---- stage W2 into the same region (w1s dead now) ----
    for (int i = tid; i < DIN_P * DHID_P; i += NT) {
        int n = i / DHID_P, k = i - n * DHID_P;
        float v = (n < DIN && k < DHID) ? W2[n * DHID + k] : 0.f;
        ws[n * W2_STRIDE + k] = tf32r(v);
    }
    __syncthreads();

    // ================= GEMM2 (tensor): C[16tok x 80] per warp ==========
    float acc2[10][4];
    #pragma unroll
    for (int nt = 0; nt < 10; nt++)
        #pragma unroll
        for (int i = 0; i < 4; i++) acc2[nt][i] = 0.f;

    {
        const float* aptr = h1 + (tokrow + r) * H1_STRIDE + tig;
        const float* bptr = ws + r * W2_STRIDE + tig;
        #pragma unroll 1
        for (int kt = 0; kt < 25; kt++) {
            unsigned a0 = __float_as_uint(aptr[kt * 8 + 0]);               // already tf32
            unsigned a2 = __float_as_uint(aptr[kt * 8 + 4]);
            unsigned a1f = __float_as_uint(aptr[kt * 8 + 8 * H1_STRIDE + 0]);
            unsigned a3 = __float_as_uint(aptr[kt * 8 + 8 * H1_STRIDE + 4]);
            #pragma unroll
            for (int nt = 0; nt < 10; nt++) {
                const float* bp = bptr + nt * 8 * W2_STRIDE + kt * 8;
                unsigned b0 = __float_as_uint(bp[0]);
                unsigned b1f = __float_as_uint(bp[4]);
                mma_tf32(acc2[nt], a0, a1f, a2, a3, b0, b1f);
            }
        }
    }

    // ======== bias + PReLU + LayerNorm(78) + residual + store ==========
    {
        float s0 = 0.f, q0 = 0.f, s1 = 0.f, q1 = 0.f;
        #pragma unroll
        for (int nt = 0; nt < 10; nt++) {
            int f0 = nt * 8 + 2 * tig;
            float2 bb = *(const float2*)&b2s[f0];
            float v;
            v = acc2[nt][0] + bb.x; v = (v >= 0.f) ? v : a2v * v; if (f0     >= DIN) v = 0.f;
            acc2[nt][0] = v; s0 += v; q0 += v * v;
            v = acc2[nt][1] + bb.y; v = (v >= 0.f) ? v : a2v * v; if (f0 + 1 >= DIN) v = 0.f;
            acc2[nt][1] = v; s0 += v; q0 += v * v;
            v = acc2[nt][2] + bb.x; v = (v >= 0.f) ? v : a2v * v; if (f0     >= DIN) v = 0.f;
            acc2[nt][2] = v; s1 += v; q1 += v * v;
            v = acc2[nt][3] + bb.y; v = (v >= 0.f) ? v : a2v * v; if (f0 + 1 >= DIN) v = 0.f;
            acc2[nt][3] = v; s1 += v; q1 += v * v;
        }
        s0 += __shfl_xor_sync(0xffffffffu, s0, 1); q0 += __shfl_xor_sync(0xffffffffu, q0, 1);
        s1 += __shfl_xor_sync(0xffffffffu, s1, 1); q1 += __shfl_xor_sync(0xffffffffu, q1, 1);
        s0 += __shfl_xor_sync(0xffffffffu, s0, 2); q0 += __shfl_xor_sync(0xffffffffu, q0, 2);
        s1 += __shfl_xor_sync(0xffffffffu, s1, 2); q1 += __shfl_xor_sync(0xffffffffu, q1, 2);
        float m0 = s0 * (1.f / DIN), m1 = s1 * (1.f / DIN);
        float r0 = rsqrtf(q0 * (1.f / DIN) - m0 * m0 + 1e-5f);
        float r1 = rsqrtf(q1 * (1.f / DIN) - m1 * m1 + 1e-5f);

        const int gt0 = base + tokrow + r;
        const int gt1 = gt0 + 8;
        const size_t half = (size_t)ntok * KPS;
        const float* j0 = js + (tokrow + r) * J_STRIDE;
        const float* j1 = js + (tokrow + r + 8) * J_STRIDE;

        #pragma unroll
        for (int nt = 0; nt < 10; nt++) {
            int f0 = nt * 8 + 2 * tig;
            float2 aa = *(const float2*)&al2s[f0];
            float2 be = *(const float2*)&be2s[f0];
            float2 jr0 = *(const float2*)&j0[f0];
            float2 jr1 = *(const float2*)&j1[f0];
            float o00 = (acc2[nt][0] - m0) * r0 * aa.x + be.x + jr0.x;
            float o01 = (acc2[nt][1] - m0) * r0 * aa.y + be.y + jr0.y;
            float o10 = (acc2[nt][2] - m1) * r1 * aa.x + be.x + jr1.x;
            float o11 = (acc2[nt][3] - m1) * r1 * aa.y + be.y + jr1.y;
            #pragma unroll
            for (int j = 0; j < 2; j++) {
                int f = f0 + j;
                if (f < DIN) {
                    size_t o0 = (f < KPS) ? ((size_t)gt0 * KPS + f)
                                          : (half + (size_t)gt0 * KPS + (f - KPS));
                    size_t o1 = (f < KPS) ? ((size_t)gt1 * KPS + f)
                                          : (half + (size_t)gt1 * KPS + (f - KPS));
                    float v0 = j ? o01 : o00;
                    float v1 = j ? o11 : o10;
                    if (gt0 < ntok) out[o0] = v0;
                    if (gt1 < ntok) out[o1] = v1;
                }
            }
        }
    }
}

extern "C" void kernel_launch(void* const* d_in, const int* in_sizes, int n_in,
                              void* d_out, int out_size) {
    const float* x      = (const float*)d_in[0];
    const float* y      = (const float*)d_in[1];
    const float* W1     = (const float*)d_in[2];
    const float* b1     = (const float*)d_in[3];
    const float* W2     = (const float*)d_in[4];
    const float* b2     = (const float*)d_in[5];
    const float* a1     = (const float*)d_in[6];
    const float* a2     = (const float*)d_in[7];
    const float* alpha1 = (const float*)d_in[8];
    const float* beta1  = (const float*)d_in[9];
    const float* alpha2 = (const float*)d_in[10];
    const float* beta2  = (const float*)d_in[11];
    float* out = (float*)d_out;

    int ntok = in_sizes[0] / KPS;
    int grid = (ntok + TB - 1) / TB;
    size_t smem = SMEM_FLOATS * sizeof(float);

    cudaFuncSetAttribute(spatialctx_tc_kernel,
                         cudaFuncAttributeMaxDynamicSharedMemorySize, (int)smem);
    spatialctx_tc_kernel<<<grid, NT, smem>>>(
        x, y, W1, b1, W2, b2, a1, a2, alpha1, beta1, alpha2, beta2, out, ntok);
}

// round 3
// speedup vs baseline: 4.2742x; 2.4603x over previous
#include <cuda_runtime.h>

#define KPS   39
#define DIN   78
#define DHID  195
#define TB    128      // tokens per block
#define NT    256      // threads per block (8 warps, 16 tokens each)

// smem strides (floats) — bank-conflict-free for all fragment accesses
#define J_STRIDE  84    // js[t][d]   t<128, d<80
#define H1_STRIDE 204   // h1[t][h]   t<128, h<200

// float offsets into dynamic smem
#define OFS_W   0                  // 16000 floats (w1 frags, later w2 frags overlay)
#define OFS_J   16000              // 128*84 = 10752
#define OFS_H1  26752              // 128*204 = 26112
#define OFS_B1  52864              // 200
#define OFS_AL1 53064
#define OFS_BE1 53264
#define OFS_B2  53464              // 80
#define OFS_AL2 53544
#define OFS_BE2 53624
#define SMEM_FLOATS 53704          // 214816 bytes

// weight fragment scratch (prepped once per launch)
__device__ float g_w1f[16000];     // [kt*25+nt][lane][2]   kt<10, nt<25
__device__ float g_w2f[16000];     // [kt*10+nt][lane][2]   kt<25, nt<10

__device__ __forceinline__ float tf32r(float f) {
    unsigned u;
    asm("cvt.rna.tf32.f32 %0, %1;" : "=r"(u) : "f"(f));
    return __uint_as_float(u);
}

__device__ __forceinline__ void mma_tf32(float c[4],
                                         unsigned a0, unsigned a1, unsigned a2, unsigned a3,
                                         unsigned b0, unsigned b1) {
    asm volatile(
        "mma.sync.aligned.m16n8k8.row.col.f32.tf32.tf32.f32 "
        "{%0,%1,%2,%3}, {%4,%5,%6,%7}, {%8,%9}, {%0,%1,%2,%3};"
        : "+f"(c[0]), "+f"(c[1]), "+f"(c[2]), "+f"(c[3])
        : "r"(a0), "r"(a1), "r"(a2), "r"(a3), "r"(b0), "r"(b1));
}

// ---------- prep: round weights to tf32, swizzle to fragment layout ----------
__global__ void prep_weights_kernel(const float* __restrict__ W1,
                                    const float* __restrict__ W2)
{
    int o = blockIdx.x * 256 + threadIdx.x;       // 0..31999
    if (o < 16000) {
        int which = o & 1;
        int lane  = (o >> 1) & 31;
        int frag  = o >> 6;                        // kt*25 + nt, < 250
        int gid = lane >> 2, tig = lane & 3;
        int kt = frag / 25, nt = frag - kt * 25;
        int k = kt * 8 + tig + 4 * which;          // < 80
        int n = nt * 8 + gid;                      // < 200
        float v = (n < DHID && k < DIN) ? W1[n * DIN + k] : 0.f;
        g_w1f[o] = tf32r(v);
    } else if (o < 32000) {
        int o2 = o - 16000;
        int which = o2 & 1;
        int lane  = (o2 >> 1) & 31;
        int frag  = o2 >> 6;                       // kt*10 + nt, < 250
        int gid = lane >> 2, tig = lane & 3;
        int kt = frag / 10, nt = frag - kt * 10;
        int k = kt * 8 + tig + 4 * which;          // < 200
        int n = nt * 8 + gid;                      // < 80
        float v = (n < DIN && k < DHID) ? W2[n * DHID + k] : 0.f;
        g_w2f[o2] = tf32r(v);
    }
}

// --------------------------------- main ---------------------------------
__global__ __launch_bounds__(NT)
void spatialctx_tc_kernel(
    const float* __restrict__ x, const float* __restrict__ y,
    const float* __restrict__ b1, const float* __restrict__ b2,
    const float* __restrict__ a1, const float* __restrict__ a2,
    const float* __restrict__ alpha1, const float* __restrict__ beta1,
    const float* __restrict__ alpha2, const float* __restrict__ beta2,
    float* __restrict__ out, int ntok)
{
    extern __shared__ float sm[];
    float* ws   = sm + OFS_W;
    float* js   = sm + OFS_J;
    float* h1   = sm + OFS_H1;
    float* b1s  = sm + OFS_B1;
    float* al1s = sm + OFS_AL1;
    float* be1s = sm + OFS_BE1;
    float* b2s  = sm + OFS_B2;
    float* al2s = sm + OFS_AL2;
    float* be2s = sm + OFS_BE2;

    const int tid  = threadIdx.x;
    const int base = blockIdx.x * TB;

    // ---- stage W1 fragments (vectorized copy, no math) ----
    {
        const float4* src = (const float4*)g_w1f;
        float4* dst = (float4*)ws;
        #pragma unroll
        for (int i = 0; i < 15; i++) dst[tid + i * NT] = src[tid + i * NT];
        if (tid + 15 * NT < 4000) dst[tid + 15 * NT] = src[tid + 15 * NT];
    }
    // ---- joined tile (exact fp32; residual needs it unrounded) ----
    {
        int t = tid >> 1, half = tid & 1;
        int gt = base + t;
        float* jrow = js + t * J_STRIDE + half * 40;
        if (gt < ntok) {
            const float* xr = x + (size_t)gt * KPS;
            const float* yr = y + (size_t)gt * KPS;
            #pragma unroll
            for (int i = 0; i < 40; i++) {
                int d = half * 40 + i;
                float v = (d < KPS) ? xr[d] : (d < DIN ? yr[d - KPS] : 0.f);
                jrow[i] = v;
            }
        } else {
            #pragma unroll
            for (int i = 0; i < 40; i++) jrow[i] = 0.f;
        }
    }
    // ---- params (zero-padded) ----
    if (tid < 200) {
        b1s[tid]  = (tid < DHID) ? b1[tid]     : 0.f;
        al1s[tid] = (tid < DHID) ? alpha1[tid] : 0.f;
        be1s[tid] = (tid < DHID) ? beta1[tid]  : 0.f;
    }
    if (tid < 80) {
        b2s[tid]  = (tid < DIN) ? b2[tid]     : 0.f;
        al2s[tid] = (tid < DIN) ? alpha2[tid] : 0.f;
        be2s[tid] = (tid < DIN) ? beta2[tid]  : 0.f;
    }
    const float a1v = a1[0];
    const float a2v = a2[0];
    __syncthreads();

    const int warp   = tid >> 5;
    const int lane   = tid & 31;
    const int r      = lane >> 2;     // group id: rows r, r+8
    const int tig    = lane & 3;      // thread-in-group
    const int tokrow = warp * 16;

    // ================= GEMM1 (tensor): C[16tok x 200hid] per warp =======
    float acc[25][4];
    #pragma unroll
    for (int nt = 0; nt < 25; nt++)
        #pragma unroll
        for (int i = 0; i < 4; i++) acc[nt][i] = 0.f;

    {
        const float*  aptr = js + (tokrow + r) * J_STRIDE + tig;
        const float2* bfr  = (const float2*)ws + lane;
        #pragma unroll 2
        for (int kt = 0; kt < 10; kt++) {
            unsigned a0 = __float_as_uint(tf32r(aptr[kt * 8 + 0]));
            unsigned a2 = __float_as_uint(tf32r(aptr[kt * 8 + 4]));
            unsigned a1f = __float_as_uint(tf32r(aptr[kt * 8 + 8 * J_STRIDE + 0]));
            unsigned a3 = __float_as_uint(tf32r(aptr[kt * 8 + 8 * J_STRIDE + 4]));
            const float2* bp = bfr + kt * 25 * 32;
            #pragma unroll
            for (int nt = 0; nt < 25; nt++) {
                float2 b = bp[nt * 32];
                mma_tf32(acc[nt], a0, a1f, a2, a3,
                         __float_as_uint(b.x), __float_as_uint(b.y));
            }
        }
    }

    // ======== bias + PReLU + LayerNorm(195) in-register ================
    {
        float s0 = 0.f, q0 = 0.f, s1 = 0.f, q1 = 0.f;
        #pragma unroll
        for (int nt = 0; nt < 25; nt++) {
            int f0 = nt * 8 + 2 * tig;
            float2 bb = *(const float2*)&b1s[f0];
            float v;
            v = acc[nt][0] + bb.x; v = (v >= 0.f) ? v : a1v * v; if (f0     >= DHID) v = 0.f;
            acc[nt][0] = v; s0 += v; q0 += v * v;
            v = acc[nt][1] + bb.y; v = (v >= 0.f) ? v : a1v * v; if (f0 + 1 >= DHID) v = 0.f;
            acc[nt][1] = v; s0 += v; q0 += v * v;
            v = acc[nt][2] + bb.x; v = (v >= 0.f) ? v : a1v * v; if (f0     >= DHID) v = 0.f;
            acc[nt][2] = v; s1 += v; q1 += v * v;
            v = acc[nt][3] + bb.y; v = (v >= 0.f) ? v : a1v * v; if (f0 + 1 >= DHID) v = 0.f;
            acc[nt][3] = v; s1 += v; q1 += v * v;
        }
        s0 += __shfl_xor_sync(0xffffffffu, s0, 1); q0 += __shfl_xor_sync(0xffffffffu, q0, 1);
        s1 += __shfl_xor_sync(0xffffffffu, s1, 1); q1 += __shfl_xor_sync(0xffffffffu, q1, 1);
        s0 += __shfl_xor_sync(0xffffffffu, s0, 2); q0 += __shfl_xor_sync(0xffffffffu, q0, 2);
        s1 += __shfl_xor_sync(0xffffffffu, s1, 2); q1 += __shfl_xor_sync(0xffffffffu, q1, 2);
        float m0 = s0 * (1.f / DHID), m1 = s1 * (1.f / DHID);
        float r0 = rsqrtf(q0 * (1.f / DHID) - m0 * m0 + 1e-5f);
        float r1 = rsqrtf(q1 * (1.f / DHID) - m1 * m1 + 1e-5f);

        float* h1w0 = h1 + (tokrow + r) * H1_STRIDE;
        float* h1w1 = h1 + (tokrow + r + 8) * H1_STRIDE;
        #pragma unroll
        for (int nt = 0; nt < 25; nt++) {
            int f0 = nt * 8 + 2 * tig;
            float2 aa = *(const float2*)&al1s[f0];
            float2 be = *(const float2*)&be1s[f0];
            float2 o0, o1;
            o0.x = tf32r((acc[nt][0] - m0) * r0 * aa.x + be.x);
            o0.y = tf32r((acc[nt][1] - m0) * r0 * aa.y + be.y);
            o1.x = tf32r((acc[nt][2] - m1) * r1 * aa.x + be.x);
            o1.y = tf32r((acc[nt][3] - m1) * r1 * aa.y + be.y);
            *(float2*)&h1w0[f0] = o0;
            *(float2*)&h1w1[f0] = o1;
        }
    }
    __syncthreads();

    // ---- stage W2 fragments into the same region (w1 frags dead) ----
    {
        const float4* src = (const float4*)g_w2f;
        float4* dst = (float4*)ws;
        #pragma unroll
        for (int i = 0; i < 15; i++) dst[tid + i * NT] = src[tid + i * NT];
        if (tid + 15 * NT < 4000) dst[tid + 15 * NT] = src[tid + 15 * NT];
    }
    __syncthreads();

    // ================= GEMM2 (tensor): C[16tok x 80] per warp ==========
    float acc2[10][4];
    #pragma unroll
    for (int nt = 0; nt < 10; nt++)
        #pragma unroll
        for (int i = 0; i < 4; i++) acc2[nt][i] = 0.f;

    {
        const float*  aptr = h1 + (tokrow + r) * H1_STRIDE + tig;
        const float2* bfr  = (const float2*)ws + lane;
        #pragma unroll 2
        for (int kt = 0; kt < 25; kt++) {
            unsigned a0 = __float_as_uint(aptr[kt * 8 + 0]);            // already tf32
            unsigned a2 = __float_as_uint(aptr[kt * 8 + 4]);
            unsigned a1f = __float_as_uint(aptr[kt * 8 + 8 * H1_STRIDE + 0]);
            unsigned a3 = __float_as_uint(aptr[kt * 8 + 8 * H1_STRIDE + 4]);
            const float2* bp = bfr + kt * 10 * 32;
            #pragma unroll
            for (int nt = 0; nt < 10; nt++) {
                float2 b = bp[nt * 32];
                mma_tf32(acc2[nt], a0, a1f, a2, a3,
                         __float_as_uint(b.x), __float_as_uint(b.y));
            }
        }
    }

    // ======== bias + PReLU + LayerNorm(78) + residual + store ==========
    {
        float s0 = 0.f, q0 = 0.f, s1 = 0.f, q1 = 0.f;
        #pragma unroll
        for (int nt = 0; nt < 10; nt++) {
            int f0 = nt * 8 + 2 * tig;
            float2 bb = *(const float2*)&b2s[f0];
            float v;
            v = acc2[nt][0] + bb.x; v = (v >= 0.f) ? v : a2v * v; if (f0     >= DIN) v = 0.f;
            acc2[nt][0] = v; s0 += v; q0 += v * v;
            v = acc2[nt][1] + bb.y; v = (v >= 0.f) ? v : a2v * v; if (f0 + 1 >= DIN) v = 0.f;
            acc2[nt][1] = v; s0 += v; q0 += v * v;
            v = acc2[nt][2] + bb.x; v = (v >= 0.f) ? v : a2v * v; if (f0     >= DIN) v = 0.f;
            acc2[nt][2] = v; s1 += v; q1 += v * v;
            v = acc2[nt][3] + bb.y; v = (v >= 0.f) ? v : a2v * v; if (f0 + 1 >= DIN) v = 0.f;
            acc2[nt][3] = v; s1 += v; q1 += v * v;
        }
        s0 += __shfl_xor_sync(0xffffffffu, s0, 1); q0 += __shfl_xor_sync(0xffffffffu, q0, 1);
        s1 += __shfl_xor_sync(0xffffffffu, s1, 1); q1 += __shfl_xor_sync(0xffffffffu, q1, 1);
        s0 += __shfl_xor_sync(0xffffffffu, s0, 2); q0 += __shfl_xor_sync(0xffffffffu, q0, 2);
        s1 += __shfl_xor_sync(0xffffffffu, s1, 2); q1 += __shfl_xor_sync(0xffffffffu, q1, 2);
        float m0 = s0 * (1.f / DIN), m1 = s1 * (1.f / DIN);
        float r0 = rsqrtf(q0 * (1.f / DIN) - m0 * m0 + 1e-5f);
        float r1 = rsqrtf(q1 * (1.f / DIN) - m1 * m1 + 1e-5f);

        const int gt0 = base + tokrow + r;
        const int gt1 = gt0 + 8;
        const size_t half = (size_t)ntok * KPS;
        const float* j0 = js + (tokrow + r) * J_STRIDE;
        const float* j1 = js + (tokrow + r + 8) * J_STRIDE;

        #pragma unroll
        for (int nt = 0; nt < 10; nt++) {
            int f0 = nt * 8 + 2 * tig;
            float2 aa = *(const float2*)&al2s[f0];
            float2 be = *(const float2*)&be2s[f0];
            float2 jr0 = *(const float2*)&j0[f0];
            float2 jr1 = *(const float2*)&j1[f0];
            float o00 = (acc2[nt][0] - m0) * r0 * aa.x + be.x + jr0.x;
            float o01 = (acc2[nt][1] - m0) * r0 * aa.y + be.y + jr0.y;
            float o10 = (acc2[nt][2] - m1) * r1 * aa.x + be.x + jr1.x;
            float o11 = (acc2[nt][3] - m1) * r1 * aa.y + be.y + jr1.y;
            #pragma unroll
            for (int j = 0; j < 2; j++) {
                int f = f0 + j;
                if (f < DIN) {
                    size_t o0 = (f < KPS) ? ((size_t)gt0 * KPS + f)
                                          : (half + (size_t)gt0 * KPS + (f - KPS));
                    size_t o1 = (f < KPS) ? ((size_t)gt1 * KPS + f)
                                          : (half + (size_t)gt1 * KPS + (f - KPS));
                    float v0 = j ? o01 : o00;
                    float v1 = j ? o11 : o10;
                    if (gt0 < ntok) out[o0] = v0;
                    if (gt1 < ntok) out[o1] = v1;
                }
            }
        }
    }
}

extern "C" void kernel_launch(void* const* d_in, const int* in_sizes, int n_in,
                              void* d_out, int out_size) {
    const float* x      = (const float*)d_in[0];
    const float* y      = (const float*)d_in[1];
    const float* W1     = (const float*)d_in[2];
    const float* b1     = (const float*)d_in[3];
    const float* W2     = (const float*)d_in[4];
    const float* b2     = (const float*)d_in[5];
    const float* a1     = (const float*)d_in[6];
    const float* a2     = (const float*)d_in[7];
    const float* alpha1 = (const float*)d_in[8];
    const float* beta1  = (const float*)d_in[9];
    const float* alpha2 = (const float*)d_in[10];
    const float* beta2  = (const float*)d_in[11];
    float* out = (float*)d_out;

    int ntok = in_sizes[0] / KPS;
    int grid = (ntok + TB - 1) / TB;
    size_t smem = SMEM_FLOATS * sizeof(float);

    prep_weights_kernel<<<125, 256>>>(W1, W2);

    cudaFuncSetAttribute(spatialctx_tc_kernel,
                         cudaFuncAttributeMaxDynamicSharedMemorySize, (int)smem);
    spatialctx_tc_kernel<<<grid, NT, smem>>>(
        x, y, b1, b2, a1, a2, alpha1, beta1, alpha2, beta2, out, ntok);
}

// round 4
// speedup vs baseline: 5.0228x; 1.1752x over previous
#include <cuda_runtime.h>

#define KPS   39
#define DIN   78
#define DHID  195
#define TB    128      // tokens per block
#define NT    256      // 8 warps, 16 tokens each

#define J_STRIDE  84   // js[t][d] t<128, d<80

// float offsets into dynamic smem
#define OFS_WS    0        // 16000 floats: w1 frags, then w2 frags overlay
#define OFS_J     16000    // 128*84 = 10752
#define OFS_B1    26752    // 200
#define OFS_ALBE1 26952    // 200 float2 = 400 floats
#define OFS_B2    27352    // 80
#define OFS_ALBE2 27432    // 80 float2 = 160 floats
#define SMEM_FLOATS 27592  // 110368 bytes -> 2 CTAs/SM

// weight fragment scratch (prepped once per launch)
// w1f: per kt (10): 12 nt-pairs [p][lane][4] (1536 fl) + single nt=24 [lane][2] (64 fl) = 1600 fl
__device__ float g_w1f[16000];
// w2f: per kt (25): 5 nt-pairs [p][lane][4] = 640 fl
__device__ float g_w2f[16000];

__device__ __forceinline__ float tf32r(float f) {
    unsigned u;
    asm("cvt.rna.tf32.f32 %0, %1;" : "=r"(u) : "f"(f));
    return __uint_as_float(u);
}

__device__ __forceinline__ void mma_tf32(float c[4],
                                         unsigned a0, unsigned a1, unsigned a2, unsigned a3,
                                         unsigned b0, unsigned b1) {
    asm volatile(
        "mma.sync.aligned.m16n8k8.row.col.f32.tf32.tf32.f32 "
        "{%0,%1,%2,%3}, {%4,%5,%6,%7}, {%8,%9}, {%0,%1,%2,%3};"
        : "+f"(c[0]), "+f"(c[1]), "+f"(c[2]), "+f"(c[3])
        : "r"(a0), "r"(a1), "r"(a2), "r"(a3), "r"(b0), "r"(b1));
}

// ---------- prep: tf32-round weights, swizzle to paired fragment layout ----------
__global__ void prep_weights_kernel(const float* __restrict__ W1,
                                    const float* __restrict__ W2)
{
    int o = blockIdx.x * 256 + threadIdx.x;       // 0..31999
    if (o < 16000) {
        int kt  = o / 1600;
        int rem = o - kt * 1600;
        int n, k;
        if (rem < 1536) {
            int p    = rem >> 7;          // 0..11
            int q    = rem & 127;
            int lane = q >> 2, fi = q & 3;
            int gid = lane >> 2, tig = lane & 3;
            int nt  = 2 * p + (fi >> 1);
            n = nt * 8 + gid;
            k = kt * 8 + tig + 4 * (fi & 1);
        } else {
            int q    = rem - 1536;        // 0..63
            int lane = q >> 1, which = q & 1;
            int gid = lane >> 2, tig = lane & 3;
            n = 192 + gid;                // nt = 24
            k = kt * 8 + tig + 4 * which;
        }
        float v = (n < DHID && k < DIN) ? W1[n * DIN + k] : 0.f;
        g_w1f[o] = tf32r(v);
    } else if (o < 32000) {
        int o2  = o - 16000;
        int kt  = o2 / 640;
        int rem = o2 - kt * 640;
        int p    = rem >> 7;              // 0..4
        int q    = rem & 127;
        int lane = q >> 2, fi = q & 3;
        int gid = lane >> 2, tig = lane & 3;
        int nt  = 2 * p + (fi >> 1);
        int n = nt * 8 + gid;             // < 80
        int k = kt * 8 + tig + 4 * (fi & 1);  // < 200
        float v = (n < DIN && k < DHID) ? W2[n * DHID + k] : 0.f;
        g_w2f[o2] = tf32r(v);
    }
}

// --------------------------------- main ---------------------------------
__global__ __launch_bounds__(NT, 2)
void spatialctx_tc_kernel(
    const float* __restrict__ x, const float* __restrict__ y,
    const float* __restrict__ b1, const float* __restrict__ b2,
    const float* __restrict__ a1, const float* __restrict__ a2,
    const float* __restrict__ alpha1, const float* __restrict__ beta1,
    const float* __restrict__ alpha2, const float* __restrict__ beta2,
    float* __restrict__ out, int ntok)
{
    extern __shared__ float sm[];
    float*  ws    = sm + OFS_WS;
    float*  js    = sm + OFS_J;
    float*  b1s   = sm + OFS_B1;
    float2* albe1 = (float2*)(sm + OFS_ALBE1);
    float*  b2s   = sm + OFS_B2;
    float2* albe2 = (float2*)(sm + OFS_ALBE2);

    const int tid  = threadIdx.x;
    const int base = blockIdx.x * TB;

    // ---- stage W1 fragments (vectorized copy) ----
    {
        const float4* src = (const float4*)g_w1f;
        float4* dst = (float4*)ws;
        #pragma unroll
        for (int i = 0; i < 15; i++) dst[tid + i * NT] = src[tid + i * NT];
        if (tid + 15 * NT < 4000) dst[tid + 15 * NT] = src[tid + 15 * NT];
    }
    // ---- joined tile (exact fp32; residual + GEMM1 A source) ----
    {
        int t = tid >> 1, half = tid & 1;
        int gt = base + t;
        float* jrow = js + t * J_STRIDE + half * 40;
        if (gt < ntok) {
            const float* xr = x + (size_t)gt * KPS;
            const float* yr = y + (size_t)gt * KPS;
            #pragma unroll
            for (int i = 0; i < 40; i++) {
                int d = half * 40 + i;
                float v = (d < KPS) ? xr[d] : (d < DIN ? yr[d - KPS] : 0.f);
                jrow[i] = v;
            }
        } else {
            #pragma unroll
            for (int i = 0; i < 40; i++) jrow[i] = 0.f;
        }
    }
    // ---- params (zero-padded) ----
    if (tid < 200) {
        b1s[tid] = (tid < DHID) ? b1[tid] : 0.f;
        albe1[tid] = make_float2((tid < DHID) ? alpha1[tid] : 0.f,
                                 (tid < DHID) ? beta1[tid]  : 0.f);
    }
    if (tid < 80) {
        b2s[tid] = (tid < DIN) ? b2[tid] : 0.f;
        albe2[tid] = make_float2((tid < DIN) ? alpha2[tid] : 0.f,
                                 (tid < DIN) ? beta2[tid]  : 0.f);
    }
    const float a1v = a1[0];
    const float a2v = a2[0];
    __syncthreads();

    const int warp   = tid >> 5;
    const int lane   = tid & 31;
    const int r      = lane >> 2;     // rows r, r+8 of warp tile
    const int tig    = lane & 3;
    const int tokrow = warp * 16;

    // ================= GEMM1 (tensor): C[16tok x 200] per warp =========
    float acc[25][4];
    #pragma unroll
    for (int nt = 0; nt < 25; nt++)
        #pragma unroll
        for (int i = 0; i < 4; i++) acc[nt][i] = 0.f;

    {
        const float* aptr = js + (tokrow + r) * J_STRIDE + tig;
        #pragma unroll 2
        for (int kt = 0; kt < 10; kt++) {
            unsigned a0 = __float_as_uint(tf32r(aptr[kt * 8 + 0]));
            unsigned a2 = __float_as_uint(tf32r(aptr[kt * 8 + 4]));
            unsigned a1f = __float_as_uint(tf32r(aptr[kt * 8 + 8 * J_STRIDE + 0]));
            unsigned a3 = __float_as_uint(tf32r(aptr[kt * 8 + 8 * J_STRIDE + 4]));
            const float4* bp = (const float4*)ws + kt * 400 + lane;
            #pragma unroll
            for (int p = 0; p < 12; p++) {
                float4 b = bp[p * 32];
                mma_tf32(acc[2*p],   a0, a1f, a2, a3,
                         __float_as_uint(b.x), __float_as_uint(b.y));
                mma_tf32(acc[2*p+1], a0, a1f, a2, a3,
                         __float_as_uint(b.z), __float_as_uint(b.w));
            }
            float2 bsg = *(const float2*)(ws + kt * 1600 + 1536 + lane * 2);
            mma_tf32(acc[24], a0, a1f, a2, a3,
                     __float_as_uint(bsg.x), __float_as_uint(bsg.y));
        }
    }

    // ======== bias + PReLU + LN1 stats (in-register) ===================
    float m0, m1, rs0, rs1;
    {
        float s0 = 0.f, q0 = 0.f, s1 = 0.f, q1 = 0.f;
        #pragma unroll
        for (int nt = 0; nt < 25; nt++) {
            int f0 = nt * 8 + 2 * tig;
            float2 bb = *(const float2*)&b1s[f0];
            float v;
            v = acc[nt][0] + bb.x; v = (v >= 0.f) ? v : a1v * v; if (f0     >= DHID) v = 0.f;
            acc[nt][0] = v; s0 += v; q0 += v * v;
            v = acc[nt][1] + bb.y; v = (v >= 0.f) ? v : a1v * v; if (f0 + 1 >= DHID) v = 0.f;
            acc[nt][1] = v; s0 += v; q0 += v * v;
            v = acc[nt][2] + bb.x; v = (v >= 0.f) ? v : a1v * v; if (f0     >= DHID) v = 0.f;
            acc[nt][2] = v; s1 += v; q1 += v * v;
            v = acc[nt][3] + bb.y; v = (v >= 0.f) ? v : a1v * v; if (f0 + 1 >= DHID) v = 0.f;
            acc[nt][3] = v; s1 += v; q1 += v * v;
        }
        s0 += __shfl_xor_sync(0xffffffffu, s0, 1); q0 += __shfl_xor_sync(0xffffffffu, q0, 1);
        s1 += __shfl_xor_sync(0xffffffffu, s1, 1); q1 += __shfl_xor_sync(0xffffffffu, q1, 1);
        s0 += __shfl_xor_sync(0xffffffffu, s0, 2); q0 += __shfl_xor_sync(0xffffffffu, q0, 2);
        s1 += __shfl_xor_sync(0xffffffffu, s1, 2); q1 += __shfl_xor_sync(0xffffffffu, q1, 2);
        m0 = s0 * (1.f / DHID); m1 = s1 * (1.f / DHID);
        rs0 = rsqrtf(q0 * (1.f / DHID) - m0 * m0 + 1e-5f);
        rs1 = rsqrtf(q1 * (1.f / DHID) - m1 * m1 + 1e-5f);
    }
    __syncthreads();   // all warps done reading w1 frags

    // ---- stage W2 fragments into the same region ----
    {
        const float4* src = (const float4*)g_w2f;
        float4* dst = (float4*)ws;
        #pragma unroll
        for (int i = 0; i < 15; i++) dst[tid + i * NT] = src[tid + i * NT];
        if (tid + 15 * NT < 4000) dst[tid + 15 * NT] = src[tid + 15 * NT];
    }
    __syncthreads();

    // ======= fused: shuffle C1->A2 frags + LN1 apply + GEMM2 ==========
    float acc2[10][4];
    #pragma unroll
    for (int nt = 0; nt < 10; nt++)
        #pragma unroll
        for (int i = 0; i < 4; i++) acc2[nt][i] = 0.f;

    {
        const int srcA = (lane & ~3) | (tig >> 1);
        const int srcB = srcA + 2;
        const bool oddt = (tig & 1);
        #pragma unroll
        for (int kt = 0; kt < 25; kt++) {
            // gather raw PReLU'd values for cols tig, tig+4 (rows r, r+8)
            float v00 = __shfl_sync(0xffffffffu, acc[kt][0], srcA);
            float v01 = __shfl_sync(0xffffffffu, acc[kt][1], srcA);
            float v20 = __shfl_sync(0xffffffffu, acc[kt][2], srcA);
            float v21 = __shfl_sync(0xffffffffu, acc[kt][3], srcA);
            float w00 = __shfl_sync(0xffffffffu, acc[kt][0], srcB);
            float w01 = __shfl_sync(0xffffffffu, acc[kt][1], srcB);
            float w20 = __shfl_sync(0xffffffffu, acc[kt][2], srcB);
            float w21 = __shfl_sync(0xffffffffu, acc[kt][3], srcB);
            float raw0 = oddt ? v01 : v00;   // (row r,   col tig)
            float raw1 = oddt ? v21 : v20;   // (row r+8, col tig)
            float raw2 = oddt ? w01 : w00;   // (row r,   col tig+4)
            float raw3 = oddt ? w21 : w20;   // (row r+8, col tig+4)

            float2 ab_a = albe1[kt * 8 + tig];
            float2 ab_b = albe1[kt * 8 + tig + 4];
            unsigned a0 = __float_as_uint(tf32r((raw0 - m0) * rs0 * ab_a.x + ab_a.y));
            unsigned a1f = __float_as_uint(tf32r((raw1 - m1) * rs1 * ab_a.x + ab_a.y));
            unsigned a2 = __float_as_uint(tf32r((raw2 - m0) * rs0 * ab_b.x + ab_b.y));
            unsigned a3 = __float_as_uint(tf32r((raw3 - m1) * rs1 * ab_b.x + ab_b.y));

            const float4* bp = (const float4*)ws + kt * 160 + lane;
            #pragma unroll
            for (int p = 0; p < 5; p++) {
                float4 b = bp[p * 32];
                mma_tf32(acc2[2*p],   a0, a1f, a2, a3,
                         __float_as_uint(b.x), __float_as_uint(b.y));
                mma_tf32(acc2[2*p+1], a0, a1f, a2, a3,
                         __float_as_uint(b.z), __float_as_uint(b.w));
            }
        }
    }

    // ======== bias + PReLU + LN2 + residual + store ====================
    {
        float s0 = 0.f, q0 = 0.f, s1 = 0.f, q1 = 0.f;
        #pragma unroll
        for (int nt = 0; nt < 10; nt++) {
            int f0 = nt * 8 + 2 * tig;
            float2 bb = *(const float2*)&b2s[f0];
            float v;
            v = acc2[nt][0] + bb.x; v = (v >= 0.f) ? v : a2v * v; if (f0     >= DIN) v = 0.f;
            acc2[nt][0] = v; s0 += v; q0 += v * v;
            v = acc2[nt][1] + bb.y; v = (v >= 0.f) ? v : a2v * v; if (f0 + 1 >= DIN) v = 0.f;
            acc2[nt][1] = v; s0 += v; q0 += v * v;
            v = acc2[nt][2] + bb.x; v = (v >= 0.f) ? v : a2v * v; if (f0     >= DIN) v = 0.f;
            acc2[nt][2] = v; s1 += v; q1 += v * v;
            v = acc2[nt][3] + bb.y; v = (v >= 0.f) ? v : a2v * v; if (f0 + 1 >= DIN) v = 0.f;
            acc2[nt][3] = v; s1 += v; q1 += v * v;
        }
        s0 += __shfl_xor_sync(0xffffffffu, s0, 1); q0 += __shfl_xor_sync(0xffffffffu, q0, 1);
        s1 += __shfl_xor_sync(0xffffffffu, s1, 1); q1 += __shfl_xor_sync(0xffffffffu, q1, 1);
        s0 += __shfl_xor_sync(0xffffffffu, s0, 2); q0 += __shfl_xor_sync(0xffffffffu, q0, 2);
        s1 += __shfl_xor_sync(0xffffffffu, s1, 2); q1 += __shfl_xor_sync(0xffffffffu, q1, 2);
        float m0b = s0 * (1.f / DIN), m1b = s1 * (1.f / DIN);
        float r0b = rsqrtf(q0 * (1.f / DIN) - m0b * m0b + 1e-5f);
        float r1b = rsqrtf(q1 * (1.f / DIN) - m1b * m1b + 1e-5f);

        const int gt0 = base + tokrow + r;
        const int gt1 = gt0 + 8;
        const size_t half = (size_t)ntok * KPS;
        const float* j0 = js + (tokrow + r) * J_STRIDE;
        const float* j1 = js + (tokrow + r + 8) * J_STRIDE;

        #pragma unroll
        for (int nt = 0; nt < 10; nt++) {
            int f0 = nt * 8 + 2 * tig;
            float2 aa = albe2[f0];
            float2 ab = albe2[f0 + 1];
            float2 jr0 = *(const float2*)&j0[f0];
            float2 jr1 = *(const float2*)&j1[f0];
            float o00 = (acc2[nt][0] - m0b) * r0b * aa.x + aa.y + jr0.x;
            float o01 = (acc2[nt][1] - m0b) * r0b * ab.x + ab.y + jr0.y;
            float o10 = (acc2[nt][2] - m1b) * r1b * aa.x + aa.y + jr1.x;
            float o11 = (acc2[nt][3] - m1b) * r1b * ab.x + ab.y + jr1.y;
            #pragma unroll
            for (int j = 0; j < 2; j++) {
                int f = f0 + j;
                if (f < DIN) {
                    size_t o0 = (f < KPS) ? ((size_t)gt0 * KPS + f)
                                          : (half + (size_t)gt0 * KPS + (f - KPS));
                    size_t o1 = (f < KPS) ? ((size_t)gt1 * KPS + f)
                                          : (half + (size_t)gt1 * KPS + (f - KPS));
                    float v0 = j ? o01 : o00;
                    float v1 = j ? o11 : o10;
                    if (gt0 < ntok) out[o0] = v0;
                    if (gt1 < ntok) out[o1] = v1;
                }
            }
        }
    }
}

extern "C" void kernel_launch(void* const* d_in, const int* in_sizes, int n_in,
                              void* d_out, int out_size) {
    const float* x      = (const float*)d_in[0];
    const float* y      = (const float*)d_in[1];
    const float* W1     = (const float*)d_in[2];
    const float* b1     = (const float*)d_in[3];
    const float* W2     = (const float*)d_in[4];
    const float* b2     = (const float*)d_in[5];
    const float* a1     = (const float*)d_in[6];
    const float* a2     = (const float*)d_in[7];
    const float* alpha1 = (const float*)d_in[8];
    const float* beta1  = (const float*)d_in[9];
    const float* alpha2 = (const float*)d_in[10];
    const float* beta2  = (const float*)d_in[11];
    float* out = (float*)d_out;

    int ntok = in_sizes[0] / KPS;
    int grid = (ntok + TB - 1) / TB;
    size_t smem = SMEM_FLOATS * sizeof(float);

    prep_weights_kernel<<<125, 256>>>(W1, W2);

    cudaFuncSetAttribute(spatialctx_tc_kernel,
                         cudaFuncAttributeMaxDynamicSharedMemorySize, (int)smem);
    spatialctx_tc_kernel<<<grid, NT, smem>>>(
        x, y, b1, b2, a1, a2, alpha1, beta1, alpha2, beta2, out, ntok);
}

// round 5
// speedup vs baseline: 7.0336x; 1.4003x over previous
#include <cuda_runtime.h>
#include <cuda_fp16.h>

#define KPS   39
#define DIN   78
#define DHID  195
#define TB    128      // tokens per block
#define NT    256      // 8 warps, 16 tokens each

#define J_STRIDE  84   // js[t][d] fp32, t<128, d<80
#define JH_STRIDE 44   // jh[t][pk] uint (fp16x2), pk<40

// float/uint offsets into dynamic smem (1 float = 1 uint slot)
#define OFS_WS    0        // 8320 uints: w1h frags (8000), then w2h frags (8320) overlay
#define OFS_J     8320     // 128*84 = 10752 fl
#define OFS_JH    19072    // 128*44 = 5632 uints
#define OFS_B1    24704    // 200
#define OFS_ALBE1 24904    // 200 float2 = 400
#define OFS_B2    25304    // 80
#define OFS_ALBE2 25384    // 160
#define SMEM_FLOATS 25544  // 102176 bytes -> 2 CTAs/SM

// fp16 weight fragment scratch (prepped once per launch), uint = fp16x2
// w1h: per kt(5): 12 nt-pairs [p][lane][4] (1536 u) + single nt=24 [lane][2] (64 u) = 1600 u
__device__ unsigned g_w1h[8000];
// w2h: per kt(13): 5 nt-pairs [p][lane][4] = 640 u
__device__ unsigned g_w2h[8320];

__device__ __forceinline__ void mma_f16(float c[4],
                                        unsigned a0, unsigned a1, unsigned a2, unsigned a3,
                                        unsigned b0, unsigned b1) {
    asm volatile(
        "mma.sync.aligned.m16n8k16.row.col.f32.f16.f16.f32 "
        "{%0,%1,%2,%3}, {%4,%5,%6,%7}, {%8,%9}, {%0,%1,%2,%3};"
        : "+f"(c[0]), "+f"(c[1]), "+f"(c[2]), "+f"(c[3])
        : "r"(a0), "r"(a1), "r"(a2), "r"(a3), "r"(b0), "r"(b1));
}

__device__ __forceinline__ unsigned pack_h2(float lo, float hi) {
    __half2 h = __floats2half2_rn(lo, hi);
    return *(unsigned*)&h;
}

// ---------- prep: fp16-pack weights into mma fragment layout ----------
__global__ void prep_weights_kernel(const float* __restrict__ W1,
                                    const float* __restrict__ W2)
{
    int o = blockIdx.x * 256 + threadIdx.x;       // 0..16319
    if (o < 8000) {
        int kt  = o / 1600;
        int rem = o - kt * 1600;
        int n, kbase;
        if (rem < 1536) {
            int p    = rem >> 7;          // 0..11
            int q    = rem & 127;
            int lane = q >> 2, fi = q & 3;
            int gid = lane >> 2, tig = lane & 3;
            int nt  = 2 * p + (fi >> 1);
            n = nt * 8 + gid;
            kbase = kt * 16 + 2 * tig + 8 * (fi & 1);
        } else {
            int q    = rem - 1536;        // 0..63
            int lane = q >> 1, reg = q & 1;
            int gid = lane >> 2, tig = lane & 3;
            n = 192 + gid;
            kbase = kt * 16 + 2 * tig + 8 * reg;
        }
        float lo = (n < DHID && kbase     < DIN) ? W1[n * DIN + kbase]     : 0.f;
        float hi = (n < DHID && kbase + 1 < DIN) ? W1[n * DIN + kbase + 1] : 0.f;
        g_w1h[o] = pack_h2(lo, hi);
    } else if (o < 16320) {
        int o2  = o - 8000;
        int kt  = o2 / 640;
        int rem = o2 - kt * 640;
        int p    = rem >> 7;              // 0..4
        int q    = rem & 127;
        int lane = q >> 2, fi = q & 3;
        int gid = lane >> 2, tig = lane & 3;
        int nt  = 2 * p + (fi >> 1);
        int n = nt * 8 + gid;                       // < 80
        int kbase = kt * 16 + 2 * tig + 8 * (fi & 1);  // < 208
        float lo = (n < DIN && kbase     < DHID) ? W2[n * DHID + kbase]     : 0.f;
        float hi = (n < DIN && kbase + 1 < DHID) ? W2[n * DHID + kbase + 1] : 0.f;
        g_w2h[o2] = pack_h2(lo, hi);
    }
}

// --------------------------------- main ---------------------------------
__global__ __launch_bounds__(NT, 2)
void spatialctx_tc_kernel(
    const float* __restrict__ x, const float* __restrict__ y,
    const float* __restrict__ b1, const float* __restrict__ b2,
    const float* __restrict__ a1, const float* __restrict__ a2,
    const float* __restrict__ alpha1, const float* __restrict__ beta1,
    const float* __restrict__ alpha2, const float* __restrict__ beta2,
    float* __restrict__ out, int ntok)
{
    extern __shared__ float sm[];
    unsigned* ws    = (unsigned*)(sm + OFS_WS);
    float*    js    = sm + OFS_J;
    unsigned* jh    = (unsigned*)(sm + OFS_JH);
    float*    b1s   = sm + OFS_B1;
    float2*   albe1 = (float2*)(sm + OFS_ALBE1);
    float*    b2s   = sm + OFS_B2;
    float2*   albe2 = (float2*)(sm + OFS_ALBE2);

    const int tid  = threadIdx.x;
    const int base = blockIdx.x * TB;

    // ---- stage W1 fragments (8000 uints = 2000 float4) ----
    {
        const float4* src = (const float4*)g_w1h;
        float4* dst = (float4*)ws;
        #pragma unroll
        for (int i = 0; i < 8; i++) {
            int o = tid + i * NT;
            if (o < 2000) dst[o] = src[o];
        }
    }
    // ---- joined tile: fp32 (residual) + fp16 (GEMM1 A) ----
    {
        int t = tid >> 1, half = tid & 1;
        int gt = base + t;
        float*    jrow = js + t * J_STRIDE + half * 40;
        unsigned* hrow = jh + t * JH_STRIDE + half * 20;
        float v[40];
        if (gt < ntok) {
            const float* xr = x + (size_t)gt * KPS;
            const float* yr = y + (size_t)gt * KPS;
            #pragma unroll
            for (int i = 0; i < 40; i++) {
                int d = half * 40 + i;
                v[i] = (d < KPS) ? xr[d] : (d < DIN ? yr[d - KPS] : 0.f);
            }
        } else {
            #pragma unroll
            for (int i = 0; i < 40; i++) v[i] = 0.f;
        }
        #pragma unroll
        for (int i = 0; i < 40; i++) jrow[i] = v[i];
        #pragma unroll
        for (int i = 0; i < 20; i++) hrow[i] = pack_h2(v[2*i], v[2*i+1]);
    }
    // ---- params (zero-padded) ----
    if (tid < 200) {
        b1s[tid] = (tid < DHID) ? b1[tid] : 0.f;
        albe1[tid] = make_float2((tid < DHID) ? alpha1[tid] : 0.f,
                                 (tid < DHID) ? beta1[tid]  : 0.f);
    }
    if (tid < 80) {
        b2s[tid] = (tid < DIN) ? b2[tid] : 0.f;
        albe2[tid] = make_float2((tid < DIN) ? alpha2[tid] : 0.f,
                                 (tid < DIN) ? beta2[tid]  : 0.f);
    }
    const float a1v = a1[0];
    const float a2v = a2[0];
    __syncthreads();

    const int warp   = tid >> 5;
    const int lane   = tid & 31;
    const int r      = lane >> 2;     // rows r, r+8 of warp tile
    const int tig    = lane & 3;
    const int tokrow = warp * 16;

    // ================= GEMM1: C[16tok x 200] per warp, 5 k-tiles =========
    float acc[25][4];
    #pragma unroll
    for (int nt = 0; nt < 25; nt++)
        #pragma unroll
        for (int i = 0; i < 4; i++) acc[nt][i] = 0.f;

    {
        const unsigned* ar0 = jh + (tokrow + r) * JH_STRIDE + tig;
        const unsigned* ar1 = ar0 + 8 * JH_STRIDE;
        #pragma unroll
        for (int kt = 0; kt < 5; kt++) {
            unsigned a0 = ar0[kt * 8];
            unsigned a1f = ar1[kt * 8];
            unsigned a2 = ar0[kt * 8 + 4];
            unsigned a3 = ar1[kt * 8 + 4];
            const float4* bp = (const float4*)ws + kt * 400 + lane;
            #pragma unroll
            for (int p = 0; p < 12; p++) {
                float4 b = bp[p * 32];
                mma_f16(acc[2*p],   a0, a1f, a2, a3,
                        __float_as_uint(b.x), __float_as_uint(b.y));
                mma_f16(acc[2*p+1], a0, a1f, a2, a3,
                        __float_as_uint(b.z), __float_as_uint(b.w));
            }
            const uint2 bsg = *(const uint2*)(ws + kt * 1600 + 1536 + lane * 2);
            mma_f16(acc[24], a0, a1f, a2, a3, bsg.x, bsg.y);
        }
    }

    // ======== bias + PReLU + LN1 stats (in-register) ===================
    float m0, m1, rs0, rs1;
    {
        float s0 = 0.f, q0 = 0.f, s1 = 0.f, q1 = 0.f;
        #pragma unroll
        for (int nt = 0; nt < 25; nt++) {
            int f0 = nt * 8 + 2 * tig;
            float2 bb = *(const float2*)&b1s[f0];
            float v;
            v = acc[nt][0] + bb.x; v = (v >= 0.f) ? v : a1v * v; if (f0     >= DHID) v = 0.f;
            acc[nt][0] = v; s0 += v; q0 += v * v;
            v = acc[nt][1] + bb.y; v = (v >= 0.f) ? v : a1v * v; if (f0 + 1 >= DHID) v = 0.f;
            acc[nt][1] = v; s0 += v; q0 += v * v;
            v = acc[nt][2] + bb.x; v = (v >= 0.f) ? v : a1v * v; if (f0     >= DHID) v = 0.f;
            acc[nt][2] = v; s1 += v; q1 += v * v;
            v = acc[nt][3] + bb.y; v = (v >= 0.f) ? v : a1v * v; if (f0 + 1 >= DHID) v = 0.f;
            acc[nt][3] = v; s1 += v; q1 += v * v;
        }
        s0 += __shfl_xor_sync(0xffffffffu, s0, 1); q0 += __shfl_xor_sync(0xffffffffu, q0, 1);
        s1 += __shfl_xor_sync(0xffffffffu, s1, 1); q1 += __shfl_xor_sync(0xffffffffu, q1, 1);
        s0 += __shfl_xor_sync(0xffffffffu, s0, 2); q0 += __shfl_xor_sync(0xffffffffu, q0, 2);
        s1 += __shfl_xor_sync(0xffffffffu, s1, 2); q1 += __shfl_xor_sync(0xffffffffu, q1, 2);
        m0 = s0 * (1.f / DHID); m1 = s1 * (1.f / DHID);
        rs0 = rsqrtf(q0 * (1.f / DHID) - m0 * m0 + 1e-5f);
        rs1 = rsqrtf(q1 * (1.f / DHID) - m1 * m1 + 1e-5f);
    }

    // ======== LN1 apply + pack to fp16 A-fragments (no shuffles!) ======
    // C-fragment layout == m16n8k16 A-fragment layout:
    // ah[nt] = {h2(row r cols 2tig,2tig+1), h2(row r+8 same cols)} of h1 tile nt
    unsigned ah[25][2];
    {
        #pragma unroll
        for (int nt = 0; nt < 25; nt++) {
            int f0 = nt * 8 + 2 * tig;
            float2 aa = albe1[f0];
            float2 ab = albe1[f0 + 1];
            ah[nt][0] = pack_h2((acc[nt][0] - m0) * rs0 * aa.x + aa.y,
                                (acc[nt][1] - m0) * rs0 * ab.x + ab.y);
            ah[nt][1] = pack_h2((acc[nt][2] - m1) * rs1 * aa.x + aa.y,
                                (acc[nt][3] - m1) * rs1 * ab.x + ab.y);
        }
    }
    __syncthreads();   // all warps done reading w1 frags

    // ---- stage W2 fragments (8320 uints = 2080 float4) ----
    {
        const float4* src = (const float4*)g_w2h;
        float4* dst = (float4*)ws;
        #pragma unroll
        for (int i = 0; i < 9; i++) {
            int o = tid + i * NT;
            if (o < 2080) dst[o] = src[o];
        }
    }
    __syncthreads();

    // ================= GEMM2: C[16tok x 80] per warp, 13 k-tiles =======
    float acc2[10][4];
    #pragma unroll
    for (int nt = 0; nt < 10; nt++)
        #pragma unroll
        for (int i = 0; i < 4; i++) acc2[nt][i] = 0.f;

    {
        #pragma unroll
        for (int kt = 0; kt < 13; kt++) {
            unsigned a0, a1f, a2, a3;
            if (kt < 12) {
                a0 = ah[2*kt][0];   a1f = ah[2*kt][1];
                a2 = ah[2*kt+1][0]; a3  = ah[2*kt+1][1];
            } else {               // k 192..207: high half is padding
                a0 = ah[24][0]; a1f = ah[24][1]; a2 = 0u; a3 = 0u;
            }
            const float4* bp = (const float4*)ws + kt * 160 + lane;
            #pragma unroll
            for (int p = 0; p < 5; p++) {
                float4 b = bp[p * 32];
                mma_f16(acc2[2*p],   a0, a1f, a2, a3,
                        __float_as_uint(b.x), __float_as_uint(b.y));
                mma_f16(acc2[2*p+1], a0, a1f, a2, a3,
                        __float_as_uint(b.z), __float_as_uint(b.w));
            }
        }
    }

    // ======== bias + PReLU + LN2 + residual + store ====================
    {
        float s0 = 0.f, q0 = 0.f, s1 = 0.f, q1 = 0.f;
        #pragma unroll
        for (int nt = 0; nt < 10; nt++) {
            int f0 = nt * 8 + 2 * tig;
            float2 bb = *(const float2*)&b2s[f0];
            float v;
            v = acc2[nt][0] + bb.x; v = (v >= 0.f) ? v : a2v * v; if (f0     >= DIN) v = 0.f;
            acc2[nt][0] = v; s0 += v; q0 += v * v;
            v = acc2[nt][1] + bb.y; v = (v >= 0.f) ? v : a2v * v; if (f0 + 1 >= DIN) v = 0.f;
            acc2[nt][1] = v; s0 += v; q0 += v * v;
            v = acc2[nt][2] + bb.x; v = (v >= 0.f) ? v : a2v * v; if (f0     >= DIN) v = 0.f;
            acc2[nt][2] = v; s1 += v; q1 += v * v;
            v = acc2[nt][3] + bb.y; v = (v >= 0.f) ? v : a2v * v; if (f0 + 1 >= DIN) v = 0.f;
            acc2[nt][3] = v; s1 += v; q1 += v * v;
        }
        s0 += __shfl_xor_sync(0xffffffffu, s0, 1); q0 += __shfl_xor_sync(0xffffffffu, q0, 1);
        s1 += __shfl_xor_sync(0xffffffffu, s1, 1); q1 += __shfl_xor_sync(0xffffffffu, q1, 1);
        s0 += __shfl_xor_sync(0xffffffffu, s0, 2); q0 += __shfl_xor_sync(0xffffffffu, q0, 2);
        s1 += __shfl_xor_sync(0xffffffffu, s1, 2); q1 += __shfl_xor_sync(0xffffffffu, q1, 2);
        float m0b = s0 * (1.f / DIN), m1b = s1 * (1.f / DIN);
        float r0b = rsqrtf(q0 * (1.f / DIN) - m0b * m0b + 1e-5f);
        float r1b = rsqrtf(q1 * (1.f / DIN) - m1b * m1b + 1e-5f);

        const int gt0 = base + tokrow + r;
        const int gt1 = gt0 + 8;
        const size_t half = (size_t)ntok * KPS;
        const float* j0 = js + (tokrow + r) * J_STRIDE;
        const float* j1 = js + (tokrow + r + 8) * J_STRIDE;

        #pragma unroll
        for (int nt = 0; nt < 10; nt++) {
            int f0 = nt * 8 + 2 * tig;
            float2 aa = albe2[f0];
            float2 ab = albe2[f0 + 1];
            float2 jr0 = *(const float2*)&j0[f0];
            float2 jr1 = *(const float2*)&j1[f0];
            float o00 = (acc2[nt][0] - m0b) * r0b * aa.x + aa.y + jr0.x;
            float o01 = (acc2[nt][1] - m0b) * r0b * ab.x + ab.y + jr0.y;
            float o10 = (acc2[nt][2] - m1b) * r1b * aa.x + aa.y + jr1.x;
            float o11 = (acc2[nt][3] - m1b) * r1b * ab.x + ab.y + jr1.y;
            #pragma unroll
            for (int j = 0; j < 2; j++) {
                int f = f0 + j;
                if (f < DIN) {
                    size_t o0 = (f < KPS) ? ((size_t)gt0 * KPS + f)
                                          : (half + (size_t)gt0 * KPS + (f - KPS));
                    size_t o1 = (f < KPS) ? ((size_t)gt1 * KPS + f)
                                          : (half + (size_t)gt1 * KPS + (f - KPS));
                    float v0 = j ? o01 : o00;
                    float v1 = j ? o11 : o10;
                    if (gt0 < ntok) out[o0] = v0;
                    if (gt1 < ntok) out[o1] = v1;
                }
            }
        }
    }
}

extern "C" void kernel_launch(void* const* d_in, const int* in_sizes, int n_in,
                              void* d_out, int out_size) {
    const float* x      = (const float*)d_in[0];
    const float* y      = (const float*)d_in[1];
    const float* W1     = (const float*)d_in[2];
    const float* b1     = (const float*)d_in[3];
    const float* W2     = (const float*)d_in[4];
    const float* b2     = (const float*)d_in[5];
    const float* a1     = (const float*)d_in[6];
    const float* a2     = (const float*)d_in[7];
    const float* alpha1 = (const float*)d_in[8];
    const float* beta1  = (const float*)d_in[9];
    const float* alpha2 = (const float*)d_in[10];
    const float* beta2  = (const float*)d_in[11];
    float* out = (float*)d_out;

    int ntok = in_sizes[0] / KPS;
    int grid = (ntok + TB - 1) / TB;
    size_t smem = SMEM_FLOATS * sizeof(float);

    prep_weights_kernel<<<64, 256>>>(W1, W2);

    cudaFuncSetAttribute(spatialctx_tc_kernel,
                         cudaFuncAttributeMaxDynamicSharedMemorySize, (int)smem);
    spatialctx_tc_kernel<<<grid, NT, smem>>>(
        x, y, b1, b2, a1, a2, alpha1, beta1, alpha2, beta2, out, ntok);
}

// round 6
// speedup vs baseline: 9.6735x; 1.3753x over previous
#include <cuda_runtime.h>
#include <cuda_fp16.h>

#define KPS   39
#define DIN   78
#define DHID  195
#define TB    128      // tokens per tile
#define NT    256      // 8 warps, 16 tokens each

// uint offsets into dynamic smem
// ws:  w1h frags 8000 u  +  w2h frags 8320 u  (both resident)
#define OFS_WS    0
#define OFS_W2    8000
#define OFS_JH    16320    // uint[128][44]  (= half[128][88]) : 5632 u
#define OFS_B1    21952    // 200 f
#define OFS_ALBE1 22152    // 400 f
#define OFS_B2    22552    // 80 f
#define OFS_ALBE2 22632    // 160 f
#define SMEM_WORDS 22792   // 91168 bytes -> 2 CTAs/SM

#define JH_U 44            // uint stride per token row (88 halves)

// fp16 weight fragment scratch (prepped once per launch), uint = fp16x2
__device__ unsigned g_w1h[8000];   // per kt(5): 12 nt-pairs [p][lane][4] + nt=24 [lane][2]
__device__ unsigned g_w2h[8320];   // per kt(13): 5 nt-pairs [p][lane][4]

__device__ __forceinline__ void mma_f16(float c[4],
                                        unsigned a0, unsigned a1, unsigned a2, unsigned a3,
                                        unsigned b0, unsigned b1) {
    asm volatile(
        "mma.sync.aligned.m16n8k16.row.col.f32.f16.f16.f32 "
        "{%0,%1,%2,%3}, {%4,%5,%6,%7}, {%8,%9}, {%0,%1,%2,%3};"
        : "+f"(c[0]), "+f"(c[1]), "+f"(c[2]), "+f"(c[3])
        : "r"(a0), "r"(a1), "r"(a2), "r"(a3), "r"(b0), "r"(b1));
}

__device__ __forceinline__ unsigned pack_h2(float lo, float hi) {
    __half2 h = __floats2half2_rn(lo, hi);
    return *(unsigned*)&h;
}

// ---------- prep: fp16-pack weights into mma fragment layout ----------
__global__ void prep_weights_kernel(const float* __restrict__ W1,
                                    const float* __restrict__ W2)
{
    int o = blockIdx.x * 256 + threadIdx.x;       // 0..16319
    if (o < 8000) {
        int kt  = o / 1600;
        int rem = o - kt * 1600;
        int n, kbase;
        if (rem < 1536) {
            int p    = rem >> 7;
            int q    = rem & 127;
            int lane = q >> 2, fi = q & 3;
            int gid = lane >> 2, tig = lane & 3;
            int nt  = 2 * p + (fi >> 1);
            n = nt * 8 + gid;
            kbase = kt * 16 + 2 * tig + 8 * (fi & 1);
        } else {
            int q    = rem - 1536;
            int lane = q >> 1, reg = q & 1;
            int gid = lane >> 2, tig = lane & 3;
            n = 192 + gid;
            kbase = kt * 16 + 2 * tig + 8 * reg;
        }
        float lo = (n < DHID && kbase     < DIN) ? W1[n * DIN + kbase]     : 0.f;
        float hi = (n < DHID && kbase + 1 < DIN) ? W1[n * DIN + kbase + 1] : 0.f;
        g_w1h[o] = pack_h2(lo, hi);
    } else if (o < 16320) {
        int o2  = o - 8000;
        int kt  = o2 / 640;
        int rem = o2 - kt * 640;
        int p    = rem >> 7;
        int q    = rem & 127;
        int lane = q >> 2, fi = q & 3;
        int gid = lane >> 2, tig = lane & 3;
        int nt  = 2 * p + (fi >> 1);
        int n = nt * 8 + gid;
        int kbase = kt * 16 + 2 * tig + 8 * (fi & 1);
        float lo = (n < DIN && kbase     < DHID) ? W2[n * DHID + kbase]     : 0.f;
        float hi = (n < DIN && kbase + 1 < DHID) ? W2[n * DHID + kbase + 1] : 0.f;
        g_w2h[o2] = pack_h2(lo, hi);
    }
}

// --------------------------------- main (persistent) ---------------------------------
__global__ __launch_bounds__(NT, 2)
void spatialctx_tc_kernel(
    const float* __restrict__ x, const float* __restrict__ y,
    const float* __restrict__ b1, const float* __restrict__ b2,
    const float* __restrict__ a1, const float* __restrict__ a2,
    const float* __restrict__ alpha1, const float* __restrict__ beta1,
    const float* __restrict__ alpha2, const float* __restrict__ beta2,
    float* __restrict__ out, int ntok, int ntiles)
{
    extern __shared__ unsigned smu[];
    unsigned* ws    = smu + OFS_WS;
    unsigned* w2s   = smu + OFS_W2;
    unsigned* jh    = smu + OFS_JH;
    float*    b1s   = (float*)(smu + OFS_B1);
    float2*   albe1 = (float2*)(smu + OFS_ALBE1);
    float*    b2s   = (float*)(smu + OFS_B2);
    float2*   albe2 = (float2*)(smu + OFS_ALBE2);

    const int tid = threadIdx.x;

    // ---- prologue: stage both weight-fragment sets (once) ----
    {
        const float4* s1 = (const float4*)g_w1h;
        float4* d1 = (float4*)ws;
        #pragma unroll
        for (int i = 0; i < 8; i++) {
            int o = tid + i * NT;
            if (o < 2000) d1[o] = s1[o];
        }
        const float4* s2 = (const float4*)g_w2h;
        float4* d2 = (float4*)w2s;
        #pragma unroll
        for (int i = 0; i < 9; i++) {
            int o = tid + i * NT;
            if (o < 2080) d2[o] = s2[o];
        }
    }
    if (tid < 200) {
        b1s[tid] = (tid < DHID) ? b1[tid] : 0.f;
        albe1[tid] = make_float2((tid < DHID) ? alpha1[tid] : 0.f,
                                 (tid < DHID) ? beta1[tid]  : 0.f);
    }
    if (tid < 80) {
        b2s[tid] = (tid < DIN) ? b2[tid] : 0.f;
        albe2[tid] = make_float2((tid < DIN) ? alpha2[tid] : 0.f,
                                 (tid < DIN) ? beta2[tid]  : 0.f);
    }
    if (tid < 128) {       // zero the jh pad columns (halves 78..87) once
        #pragma unroll
        for (int c = 39; c < 44; c++) jh[tid * JH_U + c] = 0u;
    }
    const float a1v = a1[0];
    const float a2v = a2[0];
    __syncthreads();       // the only block-wide barrier

    const int warp   = tid >> 5;
    const int lane   = tid & 31;
    const int r      = lane >> 2;
    const int tig    = lane & 3;
    const int tokrow = warp * 16;

    unsigned* jwu = jh + tokrow * JH_U;            // warp-private rows
    __half*   jwh = (__half*)jwu;

    for (int tile = blockIdx.x; tile < ntiles; tile += gridDim.x) {
        const int tbase = tile * TB;
        const int gt0w  = tbase + tokrow;          // warp's first token

        // ---- stage warp's 16 token rows: x,y slabs are contiguous ----
        __syncwarp();
        {
            const float* xs = x + (size_t)gt0w * KPS;
            const float* ys = y + (size_t)gt0w * KPS;
            if (gt0w + 16 <= ntok) {
                #pragma unroll
                for (int i = 0; i < 20; i++) {
                    int idx = lane + 32 * i;
                    if (idx < 624) {
                        int t = idx / KPS, d = idx - t * KPS;
                        jwh[t * 88 + d]       = __float2half(xs[idx]);
                        jwh[t * 88 + d + KPS] = __float2half(ys[idx]);
                    }
                }
            } else {
                #pragma unroll
                for (int i = 0; i < 20; i++) {
                    int idx = lane + 32 * i;
                    if (idx < 624) {
                        int t = idx / KPS, d = idx - t * KPS;
                        bool ok = (gt0w + t) < ntok;
                        jwh[t * 88 + d]       = __float2half(ok ? xs[idx] : 0.f);
                        jwh[t * 88 + d + KPS] = __float2half(ok ? ys[idx] : 0.f);
                    }
                }
            }
        }
        __syncwarp();

        // ================= GEMM1: C[16tok x 200], 5 k-tiles ============
        float acc[25][4];
        #pragma unroll
        for (int nt = 0; nt < 25; nt++)
            #pragma unroll
            for (int i = 0; i < 4; i++) acc[nt][i] = 0.f;

        {
            const unsigned* ar0 = jwu + r * JH_U + tig;
            const unsigned* ar1 = ar0 + 8 * JH_U;
            #pragma unroll
            for (int kt = 0; kt < 5; kt++) {
                unsigned a0 = ar0[kt * 8];
                unsigned a1f = ar1[kt * 8];
                unsigned a2 = ar0[kt * 8 + 4];
                unsigned a3 = ar1[kt * 8 + 4];
                const float4* bp = (const float4*)ws + kt * 400 + lane;
                #pragma unroll
                for (int p = 0; p < 12; p++) {
                    float4 b = bp[p * 32];
                    mma_f16(acc[2*p],   a0, a1f, a2, a3,
                            __float_as_uint(b.x), __float_as_uint(b.y));
                    mma_f16(acc[2*p+1], a0, a1f, a2, a3,
                            __float_as_uint(b.z), __float_as_uint(b.w));
                }
                const uint2 bsg = *(const uint2*)(ws + kt * 1600 + 1536 + lane * 2);
                mma_f16(acc[24], a0, a1f, a2, a3, bsg.x, bsg.y);
            }
        }

        // ======== bias + PReLU + LN1 stats =============================
        float m0, m1, rs0, rs1;
        {
            float s0 = 0.f, q0 = 0.f, s1 = 0.f, q1 = 0.f;
            #pragma unroll
            for (int nt = 0; nt < 25; nt++) {
                int f0 = nt * 8 + 2 * tig;
                float2 bb = *(const float2*)&b1s[f0];
                float v;
                v = acc[nt][0] + bb.x; v = (v >= 0.f) ? v : a1v * v; if (f0     >= DHID) v = 0.f;
                acc[nt][0] = v; s0 += v; q0 += v * v;
                v = acc[nt][1] + bb.y; v = (v >= 0.f) ? v : a1v * v; if (f0 + 1 >= DHID) v = 0.f;
                acc[nt][1] = v; s0 += v; q0 += v * v;
                v = acc[nt][2] + bb.x; v = (v >= 0.f) ? v : a1v * v; if (f0     >= DHID) v = 0.f;
                acc[nt][2] = v; s1 += v; q1 += v * v;
                v = acc[nt][3] + bb.y; v = (v >= 0.f) ? v : a1v * v; if (f0 + 1 >= DHID) v = 0.f;
                acc[nt][3] = v; s1 += v; q1 += v * v;
            }
            s0 += __shfl_xor_sync(0xffffffffu, s0, 1); q0 += __shfl_xor_sync(0xffffffffu, q0, 1);
            s1 += __shfl_xor_sync(0xffffffffu, s1, 1); q1 += __shfl_xor_sync(0xffffffffu, q1, 1);
            s0 += __shfl_xor_sync(0xffffffffu, s0, 2); q0 += __shfl_xor_sync(0xffffffffu, q0, 2);
            s1 += __shfl_xor_sync(0xffffffffu, s1, 2); q1 += __shfl_xor_sync(0xffffffffu, q1, 2);
            m0 = s0 * (1.f / DHID); m1 = s1 * (1.f / DHID);
            rs0 = rsqrtf(q0 * (1.f / DHID) - m0 * m0 + 1e-5f);
            rs1 = rsqrtf(q1 * (1.f / DHID) - m1 * m1 + 1e-5f);
        }

        // ======== LN1 apply + pack to A-fragments (C==A layout) ========
        unsigned ah[25][2];
        #pragma unroll
        for (int nt = 0; nt < 25; nt++) {
            int f0 = nt * 8 + 2 * tig;
            float2 aa = albe1[f0];
            float2 ab = albe1[f0 + 1];
            ah[nt][0] = pack_h2((acc[nt][0] - m0) * rs0 * aa.x + aa.y,
                                (acc[nt][1] - m0) * rs0 * ab.x + ab.y);
            ah[nt][1] = pack_h2((acc[nt][2] - m1) * rs1 * aa.x + aa.y,
                                (acc[nt][3] - m1) * rs1 * ab.x + ab.y);
        }

        // ================= GEMM2: C[16tok x 80], 13 k-tiles ============
        float acc2[10][4];
        #pragma unroll
        for (int nt = 0; nt < 10; nt++)
            #pragma unroll
            for (int i = 0; i < 4; i++) acc2[nt][i] = 0.f;

        {
            #pragma unroll
            for (int kt = 0; kt < 13; kt++) {
                unsigned a0, a1f, a2, a3;
                if (kt < 12) {
                    a0 = ah[2*kt][0];   a1f = ah[2*kt][1];
                    a2 = ah[2*kt+1][0]; a3  = ah[2*kt+1][1];
                } else {
                    a0 = ah[24][0]; a1f = ah[24][1]; a2 = 0u; a3 = 0u;
                }
                const float4* bp = (const float4*)w2s + kt * 160 + lane;
                #pragma unroll
                for (int p = 0; p < 5; p++) {
                    float4 b = bp[p * 32];
                    mma_f16(acc2[2*p],   a0, a1f, a2, a3,
                            __float_as_uint(b.x), __float_as_uint(b.y));
                    mma_f16(acc2[2*p+1], a0, a1f, a2, a3,
                            __float_as_uint(b.z), __float_as_uint(b.w));
                }
            }
        }

        // ======== bias + PReLU + LN2 + residual(gmem) + store ==========
        {
            float s0 = 0.f, q0 = 0.f, s1 = 0.f, q1 = 0.f;
            #pragma unroll
            for (int nt = 0; nt < 10; nt++) {
                int f0 = nt * 8 + 2 * tig;
                float2 bb = *(const float2*)&b2s[f0];
                float v;
                v = acc2[nt][0] + bb.x; v = (v >= 0.f) ? v : a2v * v; if (f0     >= DIN) v = 0.f;
                acc2[nt][0] = v; s0 += v; q0 += v * v;
                v = acc2[nt][1] + bb.y; v = (v >= 0.f) ? v : a2v * v; if (f0 + 1 >= DIN) v = 0.f;
                acc2[nt][1] = v; s0 += v; q0 += v * v;
                v = acc2[nt][2] + bb.x; v = (v >= 0.f) ? v : a2v * v; if (f0     >= DIN) v = 0.f;
                acc2[nt][2] = v; s1 += v; q1 += v * v;
                v = acc2[nt][3] + bb.y; v = (v >= 0.f) ? v : a2v * v; if (f0 + 1 >= DIN) v = 0.f;
                acc2[nt][3] = v; s1 += v; q1 += v * v;
            }
            s0 += __shfl_xor_sync(0xffffffffu, s0, 1); q0 += __shfl_xor_sync(0xffffffffu, q0, 1);
            s1 += __shfl_xor_sync(0xffffffffu, s1, 1); q1 += __shfl_xor_sync(0xffffffffu, q1, 1);
            s0 += __shfl_xor_sync(0xffffffffu, s0, 2); q0 += __shfl_xor_sync(0xffffffffu, q0, 2);
            s1 += __shfl_xor_sync(0xffffffffu, s1, 2); q1 += __shfl_xor_sync(0xffffffffu, q1, 2);
            float m0b = s0 * (1.f / DIN), m1b = s1 * (1.f / DIN);
            float r0b = rsqrtf(q0 * (1.f / DIN) - m0b * m0b + 1e-5f);
            float r1b = rsqrtf(q1 * (1.f / DIN) - m1b * m1b + 1e-5f);

            const int gt0 = gt0w + r;
            const int gt1 = gt0 + 8;
            const bool ok0 = gt0 < ntok;
            const bool ok1 = gt1 < ntok;
            const size_t half = (size_t)ntok * KPS;
            const float* xr0 = x + (size_t)gt0 * KPS;
            const float* yr0 = y + (size_t)gt0 * KPS;
            const float* xr1 = x + (size_t)gt1 * KPS;
            const float* yr1 = y + (size_t)gt1 * KPS;

            #pragma unroll
            for (int nt = 0; nt < 10; nt++) {
                int f0 = nt * 8 + 2 * tig;
                float2 aa = albe2[f0];
                float2 ab = albe2[f0 + 1];
                #pragma unroll
                for (int j = 0; j < 2; j++) {
                    int f = f0 + j;
                    if (f < DIN) {
                        float al = j ? ab.x : aa.x;
                        float be = j ? ab.y : aa.y;
                        float c0 = j ? acc2[nt][1] : acc2[nt][0];
                        float c1 = j ? acc2[nt][3] : acc2[nt][2];
                        size_t o0 = (f < KPS) ? ((size_t)gt0 * KPS + f)
                                              : (half + (size_t)gt0 * KPS + (f - KPS));
                        size_t o1 = (f < KPS) ? ((size_t)gt1 * KPS + f)
                                              : (half + (size_t)gt1 * KPS + (f - KPS));
                        if (ok0) {
                            float jv = (f < KPS) ? xr0[f] : yr0[f - KPS];
                            out[o0] = (c0 - m0b) * r0b * al + be + jv;
                        }
                        if (ok1) {
                            float jv = (f < KPS) ? xr1[f] : yr1[f - KPS];
                            out[o1] = (c1 - m1b) * r1b * al + be + jv;
                        }
                    }
                }
            }
        }
    }
}

extern "C" void kernel_launch(void* const* d_in, const int* in_sizes, int n_in,
                              void* d_out, int out_size) {
    const float* x      = (const float*)d_in[0];
    const float* y      = (const float*)d_in[1];
    const float* W1     = (const float*)d_in[2];
    const float* b1     = (const float*)d_in[3];
    const float* W2     = (const float*)d_in[4];
    const float* b2     = (const float*)d_in[5];
    const float* a1     = (const float*)d_in[6];
    const float* a2     = (const float*)d_in[7];
    const float* alpha1 = (const float*)d_in[8];
    const float* beta1  = (const float*)d_in[9];
    const float* alpha2 = (const float*)d_in[10];
    const float* beta2  = (const float*)d_in[11];
    float* out = (float*)d_out;

    int ntok   = in_sizes[0] / KPS;
    int ntiles = (ntok + TB - 1) / TB;

    int dev = 0, nsm = 148;
    cudaGetDevice(&dev);
    cudaDeviceGetAttribute(&nsm, cudaDevAttrMultiProcessorCount, dev);
    int grid = 2 * nsm;
    if (grid > ntiles) grid = ntiles;

    size_t smem = SMEM_WORDS * sizeof(unsigned);

    prep_weights_kernel<<<64, 256>>>(W1, W2);

    cudaFuncSetAttribute(spatialctx_tc_kernel,
                         cudaFuncAttributeMaxDynamicSharedMemorySize, (int)smem);
    spatialctx_tc_kernel<<<grid, NT, smem>>>(
        x, y, b1, b2, a1, a2, alpha1, beta1, alpha2, beta2, out, ntok, ntiles);
}

// round 8
// speedup vs baseline: 10.5409x; 1.0897x over previous
#include <cuda_runtime.h>
#include <cuda_fp16.h>

#define KPS   39
#define DIN   78
#define DHID  195
#define TB    128      // tokens per tile
#define NT    256      // 8 warps, 16 tokens each

// uint offsets into dynamic smem
#define OFS_WS    0        // w1h frags 8000 u
#define OFS_W2    8000     // w2h frags 8320 u
#define OFS_JH    16320    // uint[128][44]  (= half[128][88]) : 5632 u
#define OFS_B1    21952    // 200 f
#define OFS_ALBE1 22152    // 400 f
#define OFS_B2    22552    // 80 f
#define OFS_ALBE2 22632    // 160 f
#define OFS_OSL   22792    // out slab: 8 warps x 8 rows x 80 f = 5120 f
#define SMEM_WORDS 27912   // 111648 bytes -> 2 CTAs/SM

#define JH_U 44            // uint stride per token row (88 halves)

// fp16 weight fragment scratch (prepped once per launch), uint = fp16x2
__device__ unsigned g_w1h[8000];   // per kt(5): 12 nt-pairs [p][lane][4] + nt=24 [lane][2]
__device__ unsigned g_w2h[8320];   // per kt(13): 5 nt-pairs [p][lane][4]

__device__ __forceinline__ void mma_f16(float c[4],
                                        unsigned a0, unsigned a1, unsigned a2, unsigned a3,
                                        unsigned b0, unsigned b1) {
    asm volatile(
        "mma.sync.aligned.m16n8k16.row.col.f32.f16.f16.f32 "
        "{%0,%1,%2,%3}, {%4,%5,%6,%7}, {%8,%9}, {%0,%1,%2,%3};"
        : "+f"(c[0]), "+f"(c[1]), "+f"(c[2]), "+f"(c[3])
        : "r"(a0), "r"(a1), "r"(a2), "r"(a3), "r"(b0), "r"(b1));
}

__device__ __forceinline__ unsigned pack_h2(float lo, float hi) {
    __half2 h = __floats2half2_rn(lo, hi);
    return *(unsigned*)&h;
}

// ---------- prep: fp16-pack weights into mma fragment layout ----------
__global__ void prep_weights_kernel(const float* __restrict__ W1,
                                    const float* __restrict__ W2)
{
    int o = blockIdx.x * 256 + threadIdx.x;       // 0..16319
    if (o < 8000) {
        int kt  = o / 1600;
        int rem = o - kt * 1600;
        int n, kbase;
        if (rem < 1536) {
            int p    = rem >> 7;
            int q    = rem & 127;
            int lane = q >> 2, fi = q & 3;
            int gid = lane >> 2, tig = lane & 3;
            int nt  = 2 * p + (fi >> 1);
            n = nt * 8 + gid;
            kbase = kt * 16 + 2 * tig + 8 * (fi & 1);
        } else {
            int q    = rem - 1536;
            int lane = q >> 1, reg = q & 1;
            int gid = lane >> 2, tig = lane & 3;
            n = 192 + gid;
            kbase = kt * 16 + 2 * tig + 8 * reg;
        }
        float lo = (n < DHID && kbase     < DIN) ? W1[n * DIN + kbase]     : 0.f;
        float hi = (n < DHID && kbase + 1 < DIN) ? W1[n * DIN + kbase + 1] : 0.f;
        g_w1h[o] = pack_h2(lo, hi);
    } else if (o < 16320) {
        int o2  = o - 8000;
        int kt  = o2 / 640;
        int rem = o2 - kt * 640;
        int p    = rem >> 7;
        int q    = rem & 127;
        int lane = q >> 2, fi = q & 3;
        int gid = lane >> 2, tig = lane & 3;
        int nt  = 2 * p + (fi >> 1);
        int n = nt * 8 + gid;
        int kbase = kt * 16 + 2 * tig + 8 * (fi & 1);
        float lo = (n < DIN && kbase     < DHID) ? W2[n * DHID + kbase]     : 0.f;
        float hi = (n < DIN && kbase + 1 < DHID) ? W2[n * DHID + kbase + 1] : 0.f;
        g_w2h[o2] = pack_h2(lo, hi);
    }
}

// --------------------------------- main (persistent) ---------------------------------
__global__ __launch_bounds__(NT, 2)
void spatialctx_tc_kernel(
    const float* __restrict__ x, const float* __restrict__ y,
    const float* __restrict__ b1, const float* __restrict__ b2,
    const float* __restrict__ a1, const float* __restrict__ a2,
    const float* __restrict__ alpha1, const float* __restrict__ beta1,
    const float* __restrict__ alpha2, const float* __restrict__ beta2,
    float* __restrict__ out, int ntok, int ntiles)
{
    extern __shared__ unsigned smu[];
    unsigned* ws    = smu + OFS_WS;
    unsigned* w2s   = smu + OFS_W2;
    unsigned* jh    = smu + OFS_JH;
    float*    b1s   = (float*)(smu + OFS_B1);
    float2*   albe1 = (float2*)(smu + OFS_ALBE1);
    float*    b2s   = (float*)(smu + OFS_B2);
    float2*   albe2 = (float2*)(smu + OFS_ALBE2);
    float*    osl   = (float*)(smu + OFS_OSL);

    const int tid = threadIdx.x;

    // ---- prologue: stage both weight-fragment sets (once) ----
    {
        const float4* s1 = (const float4*)g_w1h;
        float4* d1 = (float4*)ws;
        #pragma unroll
        for (int i = 0; i < 8; i++) {
            int o = tid + i * NT;
            if (o < 2000) d1[o] = s1[o];
        }
        const float4* s2 = (const float4*)g_w2h;
        float4* d2 = (float4*)w2s;
        #pragma unroll
        for (int i = 0; i < 9; i++) {
            int o = tid + i * NT;
            if (o < 2080) d2[o] = s2[o];
        }
    }
    if (tid < 200) {
        b1s[tid] = (tid < DHID) ? b1[tid] : 0.f;
        albe1[tid] = make_float2((tid < DHID) ? alpha1[tid] : 0.f,
                                 (tid < DHID) ? beta1[tid]  : 0.f);
    }
    if (tid < 80) {
        b2s[tid] = (tid < DIN) ? b2[tid] : 0.f;
        albe2[tid] = make_float2((tid < DIN) ? alpha2[tid] : 0.f,
                                 (tid < DIN) ? beta2[tid]  : 0.f);
    }
    if (tid < 128) {       // zero the jh pad columns (halves 78..87) once
        #pragma unroll
        for (int c = 39; c < 44; c++) jh[tid * JH_U + c] = 0u;
    }
    const float a1v = a1[0];
    const float a2v = a2[0];
    __syncthreads();       // the only block-wide barrier

    const int warp   = tid >> 5;
    const int lane   = tid & 31;
    const int r      = lane >> 2;
    const int tig    = lane & 3;
    const int tokrow = warp * 16;

    unsigned* jwu  = jh + tokrow * JH_U;            // warp-private rows
    __half*   jwh  = (__half*)jwu;
    float*    oslw = osl + warp * 640;              // warp-private 8x80 slab

    for (int tile = blockIdx.x; tile < ntiles; tile += gridDim.x) {
        const int tbase = tile * TB;
        const int gt0w  = tbase + tokrow;          // warp's first token

        // ---- stage warp's 16 token rows: x,y slabs are contiguous ----
        __syncwarp();
        {
            const float* xs = x + (size_t)gt0w * KPS;
            const float* ys = y + (size_t)gt0w * KPS;
            if (gt0w + 16 <= ntok) {
                #pragma unroll
                for (int i = 0; i < 20; i++) {
                    int idx = lane + 32 * i;
                    if (idx < 624) {
                        int t = idx / KPS, d = idx - t * KPS;
                        jwh[t * 88 + d]       = __float2half(xs[idx]);
                        jwh[t * 88 + d + KPS] = __float2half(ys[idx]);
                    }
                }
            } else {
                #pragma unroll
                for (int i = 0; i < 20; i++) {
                    int idx = lane + 32 * i;
                    if (idx < 624) {
                        int t = idx / KPS, d = idx - t * KPS;
                        bool ok = (gt0w + t) < ntok;
                        jwh[t * 88 + d]       = __float2half(ok ? xs[idx] : 0.f);
                        jwh[t * 88 + d + KPS] = __float2half(ok ? ys[idx] : 0.f);
                    }
                }
            }
        }
        __syncwarp();

        // ================= GEMM1: C[16tok x 200], 5 k-tiles ============
        float acc[25][4];
        #pragma unroll
        for (int nt = 0; nt < 25; nt++)
            #pragma unroll
            for (int i = 0; i < 4; i++) acc[nt][i] = 0.f;

        {
            const unsigned* ar0 = jwu + r * JH_U + tig;
            const unsigned* ar1 = ar0 + 8 * JH_U;
            #pragma unroll
            for (int kt = 0; kt < 5; kt++) {
                unsigned a0 = ar0[kt * 8];
                unsigned a1f = ar1[kt * 8];
                unsigned a2 = ar0[kt * 8 + 4];
                unsigned a3 = ar1[kt * 8 + 4];
                const float4* bp = (const float4*)ws + kt * 400 + lane;
                #pragma unroll
                for (int p = 0; p < 12; p++) {
                    float4 b = bp[p * 32];
                    mma_f16(acc[2*p],   a0, a1f, a2, a3,
                            __float_as_uint(b.x), __float_as_uint(b.y));
                    mma_f16(acc[2*p+1], a0, a1f, a2, a3,
                            __float_as_uint(b.z), __float_as_uint(b.w));
                }
                const uint2 bsg = *(const uint2*)(ws + kt * 1600 + 1536 + lane * 2);
                mma_f16(acc[24], a0, a1f, a2, a3, bsg.x, bsg.y);
            }
        }

        // ======== bias + PReLU + LN1 stats =============================
        float m0, m1, rs0, rs1;
        {
            float s0 = 0.f, q0 = 0.f, s1 = 0.f, q1 = 0.f;
            #pragma unroll
            for (int nt = 0; nt < 25; nt++) {
                int f0 = nt * 8 + 2 * tig;
                float2 bb = *(const float2*)&b1s[f0];
                float v;
                v = acc[nt][0] + bb.x; v = (v >= 0.f) ? v : a1v * v; if (f0     >= DHID) v = 0.f;
                acc[nt][0] = v; s0 += v; q0 += v * v;
                v = acc[nt][1] + bb.y; v = (v >= 0.f) ? v : a1v * v; if (f0 + 1 >= DHID) v = 0.f;
                acc[nt][1] = v; s0 += v; q0 += v * v;
                v = acc[nt][2] + bb.x; v = (v >= 0.f) ? v : a1v * v; if (f0     >= DHID) v = 0.f;
                acc[nt][2] = v; s1 += v; q1 += v * v;
                v = acc[nt][3] + bb.y; v = (v >= 0.f) ? v : a1v * v; if (f0 + 1 >= DHID) v = 0.f;
                acc[nt][3] = v; s1 += v; q1 += v * v;
            }
            s0 += __shfl_xor_sync(0xffffffffu, s0, 1); q0 += __shfl_xor_sync(0xffffffffu, q0, 1);
            s1 += __shfl_xor_sync(0xffffffffu, s1, 1); q1 += __shfl_xor_sync(0xffffffffu, q1, 1);
            s0 += __shfl_xor_sync(0xffffffffu, s0, 2); q0 += __shfl_xor_sync(0xffffffffu, q0, 2);
            s1 += __shfl_xor_sync(0xffffffffu, s1, 2); q1 += __shfl_xor_sync(0xffffffffu, q1, 2);
            m0 = s0 * (1.f / DHID); m1 = s1 * (1.f / DHID);
            rs0 = rsqrtf(q0 * (1.f / DHID) - m0 * m0 + 1e-5f);
            rs1 = rsqrtf(q1 * (1.f / DHID) - m1 * m1 + 1e-5f);
        }

        // ======== LN1 apply + pack to A-fragments (C==A layout) ========
        unsigned ah[25][2];
        #pragma unroll
        for (int nt = 0; nt < 25; nt++) {
            int f0 = nt * 8 + 2 * tig;
            float2 aa = albe1[f0];
            float2 ab = albe1[f0 + 1];
            ah[nt][0] = pack_h2((acc[nt][0] - m0) * rs0 * aa.x + aa.y,
                                (acc[nt][1] - m0) * rs0 * ab.x + ab.y);
            ah[nt][1] = pack_h2((acc[nt][2] - m1) * rs1 * aa.x + aa.y,
                                (acc[nt][3] - m1) * rs1 * ab.x + ab.y);
        }

        // ================= GEMM2: C[16tok x 80], 13 k-tiles ============
        float acc2[10][4];
        #pragma unroll
        for (int nt = 0; nt < 10; nt++)
            #pragma unroll
            for (int i = 0; i < 4; i++) acc2[nt][i] = 0.f;

        {
            #pragma unroll
            for (int kt = 0; kt < 13; kt++) {
                unsigned a0, a1f, a2, a3;
                if (kt < 12) {
                    a0 = ah[2*kt][0];   a1f = ah[2*kt][1];
                    a2 = ah[2*kt+1][0]; a3  = ah[2*kt+1][1];
                } else {
                    a0 = ah[24][0]; a1f = ah[24][1]; a2 = 0u; a3 = 0u;
                }
                const float4* bp = (const float4*)w2s + kt * 160 + lane;
                #pragma unroll
                for (int p = 0; p < 5; p++) {
                    float4 b = bp[p * 32];
                    mma_f16(acc2[2*p],   a0, a1f, a2, a3,
                            __float_as_uint(b.x), __float_as_uint(b.y));
                    mma_f16(acc2[2*p+1], a0, a1f, a2, a3,
                            __float_as_uint(b.z), __float_as_uint(b.w));
                }
            }
        }

        // ======== bias + PReLU + LN2 stats =============================
        float m0b, m1b, r0b, r1b;
        {
            float s0 = 0.f, q0 = 0.f, s1 = 0.f, q1 = 0.f;
            #pragma unroll
            for (int nt = 0; nt < 10; nt++) {
                int f0 = nt * 8 + 2 * tig;
                float2 bb = *(const float2*)&b2s[f0];
                float v;
                v = acc2[nt][0] + bb.x; v = (v >= 0.f) ? v : a2v * v; if (f0     >= DIN) v = 0.f;
                acc2[nt][0] = v; s0 += v; q0 += v * v;
                v = acc2[nt][1] + bb.y; v = (v >= 0.f) ? v : a2v * v; if (f0 + 1 >= DIN) v = 0.f;
                acc2[nt][1] = v; s0 += v; q0 += v * v;
                v = acc2[nt][2] + bb.x; v = (v >= 0.f) ? v : a2v * v; if (f0     >= DIN) v = 0.f;
                acc2[nt][2] = v; s1 += v; q1 += v * v;
                v = acc2[nt][3] + bb.y; v = (v >= 0.f) ? v : a2v * v; if (f0 + 1 >= DIN) v = 0.f;
                acc2[nt][3] = v; s1 += v; q1 += v * v;
            }
            s0 += __shfl_xor_sync(0xffffffffu, s0, 1); q0 += __shfl_xor_sync(0xffffffffu, q0, 1);
            s1 += __shfl_xor_sync(0xffffffffu, s1, 1); q1 += __shfl_xor_sync(0xffffffffu, q1, 1);
            s0 += __shfl_xor_sync(0xffffffffu, s0, 2); q0 += __shfl_xor_sync(0xffffffffu, q0, 2);
            s1 += __shfl_xor_sync(0xffffffffu, s1, 2); q1 += __shfl_xor_sync(0xffffffffu, q1, 2);
            m0b = s0 * (1.f / DIN); m1b = s1 * (1.f / DIN);
            r0b = rsqrtf(q0 * (1.f / DIN) - m0b * m0b + 1e-5f);
            r1b = rsqrtf(q1 * (1.f / DIN) - m1b * m1b + 1e-5f);
        }

        // ======== staged epilogue: two row-half passes through smem ====
        const size_t yofs = (size_t)ntok * KPS;
        #pragma unroll
        for (int half = 0; half < 2; half++) {
            const float mb = half ? m1b : m0b;
            const float rb = half ? r1b : r0b;
            __syncwarp();
            // normalize + scatter into slab (mma layout, 2-way conflicts max)
            #pragma unroll
            for (int nt = 0; nt < 10; nt++) {
                int f0 = nt * 8 + 2 * tig;
                float2 aa = albe2[f0];
                float2 ab = albe2[f0 + 1];
                float c0 = half ? acc2[nt][2] : acc2[nt][0];
                float c1 = half ? acc2[nt][3] : acc2[nt][1];
                oslw[r * 80 + f0]     = (c0 - mb) * rb * aa.x + aa.y;
                oslw[r * 80 + f0 + 1] = (c1 - mb) * rb * ab.x + ab.y;
            }
            __syncwarp();
            // coalesced drain: 8 tokens x 78 features, residual from gmem
            const int t0 = gt0w + half * 8;
            const float* xs = x   + (size_t)t0 * KPS;
            const float* ys = y   + (size_t)t0 * KPS;
            float*       ox = out + (size_t)t0 * KPS;
            float*       oy = out + yofs + (size_t)t0 * KPS;
            if (t0 + 8 <= ntok) {
                #pragma unroll
                for (int i = 0; i < 20; i++) {
                    int idx = lane + 32 * i;
                    if (idx < 624) {
                        int t = idx / DIN, f = idx - t * DIN;
                        float v = oslw[t * 80 + f];
                        if (f < KPS) ox[t * KPS + f]       = v + xs[t * KPS + f];
                        else         oy[t * KPS + f - KPS] = v + ys[t * KPS + f - KPS];
                    }
                }
            } else {
                #pragma unroll
                for (int i = 0; i < 20; i++) {
                    int idx = lane + 32 * i;
                    if (idx < 624) {
                        int t = idx / DIN, f = idx - t * DIN;
                        if (t0 + t < ntok) {
                            float v = oslw[t * 80 + f];
                            if (f < KPS) ox[t * KPS + f]       = v + xs[t * KPS + f];
                            else         oy[t * KPS + f - KPS] = v + ys[t * KPS + f - KPS];
                        }
                    }
                }
            }
        }
    }
}

extern "C" void kernel_launch(void* const* d_in, const int* in_sizes, int n_in,
                              void* d_out, int out_size) {
    const float* x      = (const float*)d_in[0];
    const float* y      = (const float*)d_in[1];
    const float* W1     = (const float*)d_in[2];
    const float* b1     = (const float*)d_in[3];
    const float* W2     = (const float*)d_in[4];
    const float* b2     = (const float*)d_in[5];
    const float* a1     = (const float*)d_in[6];
    const float* a2     = (const float*)d_in[7];
    const float* alpha1 = (const float*)d_in[8];
    const float* beta1  = (const float*)d_in[9];
    const float* alpha2 = (const float*)d_in[10];
    const float* beta2  = (const float*)d_in[11];
    float* out = (float*)d_out;

    int ntok   = in_sizes[0] / KPS;
    int ntiles = (ntok + TB - 1) / TB;

    int dev = 0, nsm = 148;
    cudaGetDevice(&dev);
    cudaDeviceGetAttribute(&nsm, cudaDevAttrMultiProcessorCount, dev);
    int grid = 2 * nsm;
    if (grid > ntiles) grid = ntiles;

    size_t smem = SMEM_WORDS * sizeof(unsigned);

    prep_weights_kernel<<<64, 256>>>(W1, W2);

    cudaFuncSetAttribute(spatialctx_tc_kernel,
                         cudaFuncAttributeMaxDynamicSharedMemorySize, (int)smem);
    spatialctx_tc_kernel<<<grid, NT, smem>>>(
        x, y, b1, b2, a1, a2, alpha1, beta1, alpha2, beta2, out, ntok, ntiles);
}